// round 11
// baseline (speedup 1.0000x reference)
#include <cuda_runtime.h>
#include <cuda_bf16.h>
#include <math.h>

// Problem constants (shapes fixed by the reference)
#define MAX_N 50000
#define MAX_E 800000
#define MAX_G 16
#define NODE_DIM 128
#define HID 64
#define HEADS 3
#define FDIM 192            // HEADS*HID
#define NEG_SLOPE 0.2f
#define SCAN_B 1024
#define MAX_BLKS 64         // ceil(50000/1024)=49

// ------------- device scratch (static; zero-init from BSS at load) --------
// Invariant: g_deg, g_pool, g_gcount are ZERO on entry to kernel_launch and
// are re-zeroed by their consumers each run (self-cleaning).
// g_feat4 layout: [node][pair p=0..31] = 16B {h0d(2p),h0d(2p+1),
//   h1d(2p),h1d(2p+1), h2d(2p),h2d(2p+1), pad, pad} as bf16.
__device__ uint4  g_feat4[(size_t)MAX_N * 32];           // 25.6 MB
__device__ float4 g_el4[MAX_N];                          // x,y,z used
__device__ float4 g_er4[MAX_N];
__device__ int    g_deg[MAX_N];
__device__ int    g_bsum[MAX_BLKS];
__device__ int    g_rowoff[MAX_N + 1];
__device__ int    g_cursor[MAX_N];
__device__ int    g_csrsrc[MAX_E];
__device__ float  g_pool[MAX_G * HID];
__device__ float  g_gcount[MAX_G];

// ---------------- helpers ----------------
__device__ __forceinline__ void fma2(unsigned long long& d,
                                     unsigned long long a,
                                     unsigned long long b) {
    asm("fma.rn.f32x2 %0, %1, %2, %0;" : "+l"(d) : "l"(a), "l"(b));
}
__device__ __forceinline__ unsigned long long pack2(float f) {
    unsigned long long r;
    asm("mov.b64 %0, {%1, %1};" : "=l"(r) : "f"(f));
    return r;
}
__device__ __forceinline__ float leaky(float x) {
    return x > 0.f ? x : NEG_SLOPE * x;
}

// ---------------- CSR phase 1: degree histogram ----------------
__global__ void k_degree(const int* __restrict__ dst, int E) {
    int i = blockIdx.x * blockDim.x + threadIdx.x;
    if (i < E) atomicAdd(&g_deg[dst[i]], 1);
}

// ---------------- CSR phase 2a: per-block (1024-tile) sums ----------------
__global__ void __launch_bounds__(SCAN_B) k_scan_partial(int N) {
    __shared__ int ws[32];
    const int t = threadIdx.x, lane = t & 31, w = t >> 5;
    int idx = blockIdx.x * SCAN_B + t;
    int v = (idx < N) ? g_deg[idx] : 0;
    #pragma unroll
    for (int o = 16; o > 0; o >>= 1) v += __shfl_down_sync(0xffffffffu, v, o);
    if (lane == 0) ws[w] = v;
    __syncthreads();
    if (w == 0) {
        int s = ws[lane];
        #pragma unroll
        for (int o = 16; o > 0; o >>= 1) s += __shfl_down_sync(0xffffffffu, s, o);
        if (lane == 0) g_bsum[blockIdx.x] = s;
    }
}

// ------ CSR phase 2b: block-local scan + top-scan + write (+deg reset) ----
__global__ void __launch_bounds__(SCAN_B) k_scan_final(int N) {
    __shared__ int soff[MAX_BLKS];
    __shared__ int wsum[32];
    const int t = threadIdx.x, lane = t & 31, w = t >> 5;
    const int nb = gridDim.x;

    if (w == 0) {
        int v0 = (lane < nb) ? g_bsum[lane] : 0;
        int v1 = (lane + 32 < nb) ? g_bsum[lane + 32] : 0;
        int s0 = v0, s1 = v1;
        #pragma unroll
        for (int o = 1; o < 32; o <<= 1) {
            int y = __shfl_up_sync(0xffffffffu, s0, o);
            if (lane >= o) s0 += y;
            int y1 = __shfl_up_sync(0xffffffffu, s1, o);
            if (lane >= o) s1 += y1;
        }
        int tot0 = __shfl_sync(0xffffffffu, s0, 31);
        s1 += tot0;
        soff[lane] = s0 - v0;
        soff[lane + 32] = s1 - v1;
    }
    __syncthreads();
    const int off = soff[blockIdx.x];

    int idx = blockIdx.x * SCAN_B + t;
    int v = (idx < N) ? g_deg[idx] : 0;
    int x = v;
    #pragma unroll
    for (int o = 1; o < 32; o <<= 1) {
        int y = __shfl_up_sync(0xffffffffu, x, o);
        if (lane >= o) x += y;
    }
    if (lane == 31) wsum[w] = x;
    __syncthreads();
    if (w == 0) {
        int s = wsum[lane], sc = s;
        #pragma unroll
        for (int o = 1; o < 32; o <<= 1) {
            int y = __shfl_up_sync(0xffffffffu, sc, o);
            if (lane >= o) sc += y;
        }
        wsum[lane] = sc - s;
    }
    __syncthreads();

    int excl = (x - v) + wsum[w] + off;
    if (idx < N) {
        g_rowoff[idx] = excl;
        g_cursor[idx] = excl;
        g_deg[idx] = 0;                       // self-clean for next run
        if (idx == N - 1) g_rowoff[N] = excl + v;
    }
}

// ---------------- K1: 512-thread FFMA2 GEMM, fused el/er, packed bf16 ----
// BM=64 nodes, BN=192 cols (two 96-col halves per warp parity), BK=32.
// warp w: ng=w>>1 (8 nodes), ch=w&1 (col half); lane cg: 3 cols (stride-3,
// bank-conflict-free). Thread tile 8 nodes x 3 cols = 12 packed fp32x2 accs.
#define GM_BM 64
#define GM_HS 68     // h_s row stride (floats): 64 + pad, 16B-aligned rows
#define GM_WS 196    // w_s row stride (floats): 192 + pad

__global__ void __launch_bounds__(512, 1) k_gemm(
    const float* __restrict__ h, const float* __restrict__ fc_w,
    const float* __restrict__ attn_l, const float* __restrict__ attn_r, int N)
{
    __shared__ float h_s[32 * GM_HS];
    __shared__ float w_s[32 * GM_WS];
    __shared__ float s_e[2][GM_BM][3];
    __shared__ float s_r[2][GM_BM][3];

    const int tid = threadIdx.x;
    const int wid = tid >> 5;
    const int ng  = wid >> 1;          // node group (8 nodes)
    const int ch  = wid & 1;           // col half (96 cols)
    const int cg  = tid & 31;          // lane -> 3 cols: 96*ch + 3*cg + j
    const int base = blockIdx.x * GM_BM;

    const float4* h4 = (const float4*)h;      // [N][32]
    const float4* w4 = (const float4*)fc_w;   // [192][32]

    // acc2[mp][j]: packed fp32x2 over node pair (2mp,2mp+1), col 96ch+3cg+j
    unsigned long long acc2[4][3];
    #pragma unroll
    for (int mp = 0; mp < 4; mp++)
        #pragma unroll
        for (int j = 0; j < 3; j++) acc2[mp][j] = 0ull;

    #pragma unroll
    for (int chunk = 0; chunk < 4; chunk++) {
        if (chunk) __syncthreads();
        // stage h: 64 nodes x 8 float4 = 512 -> 1 per thread
        {
            int nd = tid >> 3, kq = tid & 7;
            int gn = base + nd;
            float4 v = (gn < N) ? h4[(size_t)gn * 32 + chunk * 8 + kq]
                                : make_float4(0.f, 0.f, 0.f, 0.f);
            h_s[(kq * 4 + 0) * GM_HS + nd] = v.x;
            h_s[(kq * 4 + 1) * GM_HS + nd] = v.y;
            h_s[(kq * 4 + 2) * GM_HS + nd] = v.z;
            h_s[(kq * 4 + 3) * GM_HS + nd] = v.w;
        }
        // stage w: 192 cols x 8 float4 = 1536 -> 3 per thread
        #pragma unroll
        for (int i = 0; i < 3; i++) {
            int F = i * 512 + tid;
            int c = F >> 3, kq = F & 7;
            float4 v = w4[c * 32 + chunk * 8 + kq];
            w_s[(kq * 4 + 0) * GM_WS + c] = v.x;
            w_s[(kq * 4 + 1) * GM_WS + c] = v.y;
            w_s[(kq * 4 + 2) * GM_WS + c] = v.z;
            w_s[(kq * 4 + 3) * GM_WS + c] = v.w;
        }
        __syncthreads();

        #pragma unroll 4
        for (int k = 0; k < 32; k++) {
            float4 ha = *(const float4*)&h_s[k * GM_HS + ng * 8];
            float4 hb = *(const float4*)&h_s[k * GM_HS + ng * 8 + 4];
            unsigned long long hp[4];
            hp[0] = *(unsigned long long*)&ha.x;
            hp[1] = *(unsigned long long*)&ha.z;
            hp[2] = *(unsigned long long*)&hb.x;
            hp[3] = *(unsigned long long*)&hb.z;
            const float* wr = &w_s[k * GM_WS + 96 * ch + 3 * cg];
            #pragma unroll
            for (int j = 0; j < 3; j++) {
                unsigned long long wp = pack2(wr[j]);
                fma2(acc2[0][j], hp[0], wp);
                fma2(acc2[1][j], hp[1], wp);
                fma2(acc2[2][j], hp[2], wp);
                fma2(acc2[3][j], hp[3], wp);
            }
        }
    }

    // ---- epilogue ----
    const int cbase = 96 * ch + 3 * cg;
    float alv[3], arv[3];
    #pragma unroll
    for (int j = 0; j < 3; j++) {
        alv[j] = __ldg(&attn_l[cbase + j]);
        arv[j] = __ldg(&attn_r[cbase + j]);
    }

    #pragma unroll
    for (int mp = 0; mp < 4; mp++) {
        #pragma unroll
        for (int half = 0; half < 2; half++) {
            const int nl = ng * 8 + 2 * mp + half;   // node local 0..63
            const int node = base + nl;
            float v[3];
            #pragma unroll
            for (int j = 0; j < 3; j++) {
                float2 f = *(float2*)&acc2[mp][j];
                v[j] = half ? f.y : f.x;
            }
            // per-head el/er partials
            float e0 = 0.f, e1 = 0.f, e2 = 0.f;
            float r0 = 0.f, r1 = 0.f, r2 = 0.f;
            #pragma unroll
            for (int j = 0; j < 3; j++) {
                int c = cbase + j;
                float tl = v[j] * alv[j], tr = v[j] * arv[j];
                if (c < 64)       { e0 += tl; r0 += tr; }
                else if (c < 128) { e1 += tl; r1 += tr; }
                else              { e2 += tl; r2 += tr; }
            }
            #pragma unroll
            for (int o = 16; o > 0; o >>= 1) {
                e0 += __shfl_down_sync(0xffffffffu, e0, o);
                e1 += __shfl_down_sync(0xffffffffu, e1, o);
                e2 += __shfl_down_sync(0xffffffffu, e2, o);
                r0 += __shfl_down_sync(0xffffffffu, r0, o);
                r1 += __shfl_down_sync(0xffffffffu, r1, o);
                r2 += __shfl_down_sync(0xffffffffu, r2, o);
            }
            if (cg == 0) {
                s_e[ch][nl][0] = e0; s_e[ch][nl][1] = e1; s_e[ch][nl][2] = e2;
                s_r[ch][nl][0] = r0; s_r[ch][nl][1] = r1; s_r[ch][nl][2] = r2;
            }
            // packed bf16 feat stores: [node][pair][h0,h0,h1,h1,h2,h2,pad]
            if (node < N) {
                char* rowp = (char*)&g_feat4[(size_t)node * 32];
                #pragma unroll
                for (int j = 0; j < 3; j++) {
                    int c = cbase + j;
                    int d = c & 63, hd = c >> 6;
                    int off = ((d >> 1) << 4) + (hd << 2) + ((d & 1) << 1);
                    *(__nv_bfloat16*)(rowp + off) = __float2bfloat16(v[j]);
                }
            }
        }
    }

    __syncthreads();
    if (tid < GM_BM) {
        int node = base + tid;
        if (node < N) {
            g_el4[node] = make_float4(s_e[0][tid][0] + s_e[1][tid][0],
                                      s_e[0][tid][1] + s_e[1][tid][1],
                                      s_e[0][tid][2] + s_e[1][tid][2], 0.f);
            g_er4[node] = make_float4(s_r[0][tid][0] + s_r[1][tid][0],
                                      s_r[0][tid][1] + s_r[1][tid][1],
                                      s_r[0][tid][2] + s_r[1][tid][2], 0.f);
        }
    }
}

// ---------------- CSR phase 3: scatter ----------------
__global__ void k_scatter(const int* __restrict__ src, const int* __restrict__ dst, int E) {
    int i = blockIdx.x * blockDim.x + threadIdx.x;
    if (i < E) {
        int d = dst[i];
        int pos = atomicAdd(&g_cursor[d], 1);
        g_csrsrc[pos] = src[i];
    }
}

// ---------------- K3: fused GAT softmax + aggregation + pool --------------
// warp per destination node; lane-parallel exp; ONE LDG.128 per edge per
// lane (packed feat layout); softmax sums warp-reduced once.
__global__ void __launch_bounds__(256) k_gat(
    const int* __restrict__ graph_id, const float* __restrict__ bias, int N)
{
    const int node = (blockIdx.x * blockDim.x + threadIdx.x) >> 5;
    const int lane = threadIdx.x & 31;
    if (node >= N) return;
    const int begin = g_rowoff[node];
    const int end   = g_rowoff[node + 1];

    const float4 er = g_er4[node];

    float s0 = 0.f, s1 = 0.f, s2 = 0.f;   // lane-local exp sums
    float a0 = 0.f, a1 = 0.f, a2 = 0.f, a3 = 0.f, a4 = 0.f, a5 = 0.f;

    for (int b = begin; b < end; b += 32) {
        const int i = b + lane;
        const bool act = i < end;
        int mys = act ? g_csrsrc[i] : 0;
        float4 el = g_el4[mys];
        float ex0 = __expf(leaky(el.x + er.x));
        float ex1 = __expf(leaky(el.y + er.y));
        float ex2 = __expf(leaky(el.z + er.z));
        if (act) { s0 += ex0; s1 += ex1; s2 += ex2; }

        int cnt = end - b; if (cnt > 32) cnt = 32;
        #pragma unroll 4
        for (int j = 0; j < cnt; j++) {
            int   s  = __shfl_sync(0xffffffffu, mys, j);
            float e0 = __shfl_sync(0xffffffffu, ex0, j);
            float e1 = __shfl_sync(0xffffffffu, ex1, j);
            float e2 = __shfl_sync(0xffffffffu, ex2, j);
            uint4 u = __ldg(&g_feat4[(size_t)s * 32 + lane]);
            float2 f0 = __bfloat1622float2(*(__nv_bfloat162*)&u.x);
            float2 f1 = __bfloat1622float2(*(__nv_bfloat162*)&u.y);
            float2 f2 = __bfloat1622float2(*(__nv_bfloat162*)&u.z);
            a0 += e0 * f0.x;  a1 += e0 * f0.y;
            a2 += e1 * f1.x;  a3 += e1 * f1.y;
            a4 += e2 * f2.x;  a5 += e2 * f2.y;
        }
    }

    #pragma unroll
    for (int o = 16; o > 0; o >>= 1) {
        s0 += __shfl_xor_sync(0xffffffffu, s0, o);
        s1 += __shfl_xor_sync(0xffffffffu, s1, o);
        s2 += __shfl_xor_sync(0xffffffffu, s2, o);
    }

    const bool has = end > begin;
    const float i0 = has ? 1.f / s0 : 0.f;
    const float i1 = has ? 1.f / s1 : 0.f;
    const float i2 = has ? 1.f / s2 : 0.f;

    const int d0 = 2 * lane, d1 = 2 * lane + 1;
    const float third = 1.f / 3.f;
    float hd0 = (a0 * i0 + a2 * i1 + a4 * i2
                 + bias[d0] + bias[64 + d0] + bias[128 + d0]) * third;
    float hd1 = (a1 * i0 + a3 * i1 + a5 * i2
                 + bias[d1] + bias[64 + d1] + bias[128 + d1]) * third;

    const int g = graph_id[node];
    atomicAdd(&g_pool[g * HID + d0], hd0);
    atomicAdd(&g_pool[g * HID + d1], hd1);
    if (lane == 0) atomicAdd(&g_gcount[g], 1.f);
}

// ---------------- K4: final MLP + sigmoid (+ pool reset) ----------------
__global__ void k_final(
    const float* __restrict__ z, const float* __restrict__ lin1_w,
    const float* __restrict__ lin1_b, const float* __restrict__ lin2_w,
    const float* __restrict__ lin2_b, float* __restrict__ out, int G)
{
    const int w = threadIdx.x >> 5;
    const int lane = threadIdx.x & 31;
    if (w >= G) return;

    float z1a = lin1_b[lane], z1b = lin1_b[lane + 32];
    const float* zr = &z[w * 128];
    const float* w1a = &lin1_w[lane * 128];
    const float* w1b = &lin1_w[(lane + 32) * 128];
    #pragma unroll 4
    for (int k = 0; k < 128; k++) {
        float zv = zr[k];
        z1a += zv * w1a[k];
        z1b += zv * w1b[k];
    }

    float cnt = g_gcount[w];
    float invc = 1.f / fmaxf(cnt, 1.f);
    float pa = g_pool[w * HID + lane] * invc;
    float pb = g_pool[w * HID + 32 + lane] * invc;

    // self-clean for next run
    g_pool[w * HID + lane] = 0.f;
    g_pool[w * HID + 32 + lane] = 0.f;
    if (lane == 0) g_gcount[w] = 0.f;

    float part = lin2_w[lane] * pa + lin2_w[32 + lane] * pb
               + lin2_w[64 + lane] * z1a + lin2_w[96 + lane] * z1b;
    #pragma unroll
    for (int o = 16; o > 0; o >>= 1)
        part += __shfl_down_sync(0xffffffffu, part, o);

    if (lane == 0) {
        float v = part + lin2_b[0];
        out[w] = 1.f / (1.f + expf(-v));
    }
}

// ---------------- launch ----------------
extern "C" void kernel_launch(void* const* d_in, const int* in_sizes, int n_in,
                              void* d_out, int out_size)
{
    const float* h        = (const float*)d_in[0];
    const float* z        = (const float*)d_in[1];
    const int*   src      = (const int*)  d_in[2];
    const int*   dst      = (const int*)  d_in[3];
    const int*   graph_id = (const int*)  d_in[4];
    const float* fc_w     = (const float*)d_in[5];
    const float* attn_l   = (const float*)d_in[6];
    const float* attn_r   = (const float*)d_in[7];
    const float* bias     = (const float*)d_in[8];
    const float* lin1_w   = (const float*)d_in[9];
    const float* lin1_b   = (const float*)d_in[10];
    const float* lin2_w   = (const float*)d_in[11];
    const float* lin2_b   = (const float*)d_in[12];

    const int N = in_sizes[0] / NODE_DIM;   // 50000
    const int E = in_sizes[2];              // 800000
    const int G = in_sizes[1] / 128;        // 16
    const int NB = (N + SCAN_B - 1) / SCAN_B;  // 49

    // Launch order: slot 4 (the ncu-profiled launch) = k_gemm.
    k_degree<<<(E + 255) / 256, 256>>>(dst, E);                       // 1
    k_scan_partial<<<NB, SCAN_B>>>(N);                                // 2
    k_scan_final<<<NB, SCAN_B>>>(N);                                  // 3
    k_gemm<<<(N + GM_BM - 1) / GM_BM, 512>>>(h, fc_w,                 // 4
                                             attn_l, attn_r, N);
    k_scatter<<<(E + 255) / 256, 256>>>(src, dst, E);                 // 5
    k_gat<<<(N * 32 + 255) / 256, 256>>>(graph_id, bias, N);          // 6
    k_final<<<1, 32 * G>>>(z, lin1_w, lin1_b, lin2_w, lin2_b,         // 7
                           (float*)d_out, G);
}

// round 12
// speedup vs baseline: 1.7457x; 1.7457x over previous
#include <cuda_runtime.h>
#include <cuda_bf16.h>
#include <math.h>

// Problem constants (shapes fixed by the reference)
#define MAX_N 50000
#define MAX_E 800000
#define MAX_G 16
#define NODE_DIM 128
#define HID 64
#define HEADS 3
#define FDIM 192            // HEADS*HID
#define NEG_SLOPE 0.2f
#define SCAN_B 1024
#define MAX_BLKS 64         // ceil(50000/1024)=49

// ------------- device scratch (static; zero-init from BSS at load) --------
// Self-cleaning invariants (hold at entry of every kernel_launch call):
//   g_deg == 0          (reset by k_scan_lookback after consuming)
//   g_sumflag == 0      (reset by k_scatter)
//   g_pool == 0         (reset by k_final)
// Feat layout (pad-free): per node, lane l owns dims (2l,2l+1) of each head.
//   g_featP[node*32+l] = uint2 {head0 bf16x2, head1 bf16x2}   (12.8 MB)
//   g_featQ[node*32+l] = uint  {head2 bf16x2}                 ( 6.4 MB)
__device__ uint2  g_featP[(size_t)MAX_N * 32];
__device__ unsigned int g_featQ[(size_t)MAX_N * 32];
__device__ float4 g_el4[MAX_N];                          // x,y,z used
__device__ float4 g_er4[MAX_N];
__device__ int    g_deg[MAX_N];
__device__ int    g_sumflag[MAX_BLKS];                   // tile_sum+1, 0=not ready
__device__ int    g_rowoff[MAX_N + 1];
__device__ int    g_cursor[MAX_N];
__device__ int    g_csrsrc[MAX_E];
__device__ float  g_pool[MAX_G * HID];

// ---------------- helpers ----------------
__device__ __forceinline__ void fma2(unsigned long long& d,
                                     unsigned long long a,
                                     unsigned long long b) {
    asm("fma.rn.f32x2 %0, %1, %2, %0;" : "+l"(d) : "l"(a), "l"(b));
}
__device__ __forceinline__ unsigned long long pack2(float f) {
    unsigned long long r;
    asm("mov.b64 %0, {%1, %1};" : "=l"(r) : "f"(f));
    return r;
}
__device__ __forceinline__ float leaky(float x) {
    return x > 0.f ? x : NEG_SLOPE * x;
}

// ---- K1: 512-thread FFMA2 GEMM, fused el/er, pad-free bf16 feat,
//      PLUS embedded degree histogram (independent work, overlapped). ----
#define GM_BM 64
#define GM_HS 68     // h_s row stride (floats)
#define GM_WS 196    // w_s row stride (floats)

__global__ void __launch_bounds__(512, 1) k_gemm(
    const float* __restrict__ h, const float* __restrict__ fc_w,
    const float* __restrict__ attn_l, const float* __restrict__ attn_r,
    const int* __restrict__ dst, int E, int N)
{
    __shared__ float h_s[32 * GM_HS];
    __shared__ float w_s[32 * GM_WS];
    __shared__ float s_e[2][GM_BM][3];
    __shared__ float s_r[2][GM_BM][3];

    const int tid = threadIdx.x;
    const int wid = tid >> 5;
    const int ng  = wid >> 1;          // node group (8 nodes)
    const int ch  = wid & 1;           // col half (96 cols)
    const int cg  = tid & 31;          // lane -> cols 96*ch + 3*cg + j
    const int base = blockIdx.x * GM_BM;

    const float4* h4 = (const float4*)h;      // [N][32]
    const float4* w4 = (const float4*)fc_w;   // [192][32]

    unsigned long long acc2[4][3];
    #pragma unroll
    for (int mp = 0; mp < 4; mp++)
        #pragma unroll
        for (int j = 0; j < 3; j++) acc2[mp][j] = 0ull;

    #pragma unroll
    for (int chunk = 0; chunk < 4; chunk++) {
        if (chunk) __syncthreads();
        {   // stage h: 64 nodes x 8 float4 = 512 -> 1 per thread
            int nd = tid >> 3, kq = tid & 7;
            int gn = base + nd;
            float4 v = (gn < N) ? h4[(size_t)gn * 32 + chunk * 8 + kq]
                                : make_float4(0.f, 0.f, 0.f, 0.f);
            h_s[(kq * 4 + 0) * GM_HS + nd] = v.x;
            h_s[(kq * 4 + 1) * GM_HS + nd] = v.y;
            h_s[(kq * 4 + 2) * GM_HS + nd] = v.z;
            h_s[(kq * 4 + 3) * GM_HS + nd] = v.w;
        }
        #pragma unroll
        for (int i = 0; i < 3; i++) {   // stage w: 1536 float4 -> 3 per thread
            int F = i * 512 + tid;
            int c = F >> 3, kq = F & 7;
            float4 v = w4[c * 32 + chunk * 8 + kq];
            w_s[(kq * 4 + 0) * GM_WS + c] = v.x;
            w_s[(kq * 4 + 1) * GM_WS + c] = v.y;
            w_s[(kq * 4 + 2) * GM_WS + c] = v.z;
            w_s[(kq * 4 + 3) * GM_WS + c] = v.w;
        }
        __syncthreads();

        #pragma unroll 4
        for (int k = 0; k < 32; k++) {
            float4 ha = *(const float4*)&h_s[k * GM_HS + ng * 8];
            float4 hb = *(const float4*)&h_s[k * GM_HS + ng * 8 + 4];
            unsigned long long hp[4];
            hp[0] = *(unsigned long long*)&ha.x;
            hp[1] = *(unsigned long long*)&ha.z;
            hp[2] = *(unsigned long long*)&hb.x;
            hp[3] = *(unsigned long long*)&hb.z;
            const float* wr = &w_s[k * GM_WS + 96 * ch + 3 * cg];
            #pragma unroll
            for (int j = 0; j < 3; j++) {
                unsigned long long wp = pack2(wr[j]);
                fma2(acc2[0][j], hp[0], wp);
                fma2(acc2[1][j], hp[1], wp);
                fma2(acc2[2][j], hp[2], wp);
                fma2(acc2[3][j], hp[3], wp);
            }
        }
    }

    // ---- epilogue ----
    const int cbase = 96 * ch + 3 * cg;
    float alv[3], arv[3];
    #pragma unroll
    for (int j = 0; j < 3; j++) {
        alv[j] = __ldg(&attn_l[cbase + j]);
        arv[j] = __ldg(&attn_r[cbase + j]);
    }

    #pragma unroll
    for (int mp = 0; mp < 4; mp++) {
        #pragma unroll
        for (int half = 0; half < 2; half++) {
            const int nl = ng * 8 + 2 * mp + half;
            const int node = base + nl;
            float v[3];
            #pragma unroll
            for (int j = 0; j < 3; j++) {
                float2 f = *(float2*)&acc2[mp][j];
                v[j] = half ? f.y : f.x;
            }
            float e0 = 0.f, e1 = 0.f, e2 = 0.f;
            float r0 = 0.f, r1 = 0.f, r2 = 0.f;
            #pragma unroll
            for (int j = 0; j < 3; j++) {
                int c = cbase + j;
                float tl = v[j] * alv[j], tr = v[j] * arv[j];
                if (c < 64)       { e0 += tl; r0 += tr; }
                else if (c < 128) { e1 += tl; r1 += tr; }
                else              { e2 += tl; r2 += tr; }
            }
            #pragma unroll
            for (int o = 16; o > 0; o >>= 1) {
                e0 += __shfl_down_sync(0xffffffffu, e0, o);
                e1 += __shfl_down_sync(0xffffffffu, e1, o);
                e2 += __shfl_down_sync(0xffffffffu, e2, o);
                r0 += __shfl_down_sync(0xffffffffu, r0, o);
                r1 += __shfl_down_sync(0xffffffffu, r1, o);
                r2 += __shfl_down_sync(0xffffffffu, r2, o);
            }
            if (cg == 0) {
                s_e[ch][nl][0] = e0; s_e[ch][nl][1] = e1; s_e[ch][nl][2] = e2;
                s_r[ch][nl][0] = r0; s_r[ch][nl][1] = r1; s_r[ch][nl][2] = r2;
            }
            if (node < N) {
                char* pp = (char*)g_featP + (size_t)node * 256;
                char* qq = (char*)g_featQ + (size_t)node * 128;
                #pragma unroll
                for (int j = 0; j < 3; j++) {
                    int c = cbase + j;
                    int d = c & 63, hd = c >> 6, p = d >> 1, lo = (d & 1) << 1;
                    __nv_bfloat16 b = __float2bfloat16(v[j]);
                    if (hd < 2) *(__nv_bfloat16*)(pp + p * 8 + hd * 4 + lo) = b;
                    else        *(__nv_bfloat16*)(qq + p * 4 + lo) = b;
                }
            }
        }
    }

    __syncthreads();
    if (tid < GM_BM) {
        int node = base + tid;
        if (node < N) {
            g_el4[node] = make_float4(s_e[0][tid][0] + s_e[1][tid][0],
                                      s_e[0][tid][1] + s_e[1][tid][1],
                                      s_e[0][tid][2] + s_e[1][tid][2], 0.f);
            g_er4[node] = make_float4(s_r[0][tid][0] + s_r[1][tid][0],
                                      s_r[0][tid][1] + s_r[1][tid][1],
                                      s_r[0][tid][2] + s_r[1][tid][2], 0.f);
        }
    }

    // ---- embedded degree histogram: this block's slice of edges ----
    {
        int eb = (E + gridDim.x - 1) / gridDim.x;
        int e0 = blockIdx.x * eb;
        int e1 = e0 + eb; if (e1 > E) e1 = E;
        for (int i = e0 + tid; i < e1; i += 512)
            atomicAdd(&g_deg[dst[i]], 1);
    }
}

// ------- CSR scan: single kernel, decoupled lookback (49 blocks, all
//         resident -> spin-safe). Also resets g_deg. --------------------
__global__ void __launch_bounds__(SCAN_B) k_scan_lookback(int N) {
    __shared__ int wsum[32];
    __shared__ int s_total;
    __shared__ int s_off;
    const int t = threadIdx.x, lane = t & 31, w = t >> 5;
    if (t == 0) s_off = 0;

    int idx = blockIdx.x * SCAN_B + t;
    int v = (idx < N) ? g_deg[idx] : 0;
    int x = v;
    #pragma unroll
    for (int o = 1; o < 32; o <<= 1) {
        int y = __shfl_up_sync(0xffffffffu, x, o);
        if (lane >= o) x += y;
    }
    if (lane == 31) wsum[w] = x;
    __syncthreads();
    if (w == 0) {
        int s = wsum[lane], sc = s;
        #pragma unroll
        for (int o = 1; o < 32; o <<= 1) {
            int y = __shfl_up_sync(0xffffffffu, sc, o);
            if (lane >= o) sc += y;
        }
        if (lane == 31) s_total = sc;
        wsum[lane] = sc - s;
    }
    __syncthreads();
    const int excl = (x - v) + wsum[w];

    // publish this block's tile sum (flag = sum+1; 0 means not ready)
    if (t == 0) {
        int S = s_total;
        __threadfence();
        *(volatile int*)&g_sumflag[blockIdx.x] = S + 1;
    }
    // lookback: threads 0..blockIdx.x-1 poll predecessors
    if (t < blockIdx.x) {
        volatile int* sf = g_sumflag;
        int tv;
        do { tv = sf[t]; } while (tv == 0);
        atomicAdd(&s_off, tv - 1);
    }
    __syncthreads();
    const int off = s_off;

    if (idx < N) {
        int ro = excl + off;
        g_rowoff[idx] = ro;
        g_cursor[idx] = ro;
        g_deg[idx] = 0;                      // self-clean
        if (idx == N - 1) g_rowoff[N] = ro + v;
    }
}

// ---------------- CSR scatter (+ sumflag reset) ----------------
__global__ void k_scatter(const int* __restrict__ src, const int* __restrict__ dst, int E) {
    if (blockIdx.x == 0 && threadIdx.x < MAX_BLKS)
        g_sumflag[threadIdx.x] = 0;          // self-clean for next run
    int i = blockIdx.x * blockDim.x + threadIdx.x;
    if (i < E) {
        int d = dst[i];
        int pos = atomicAdd(&g_cursor[d], 1);
        g_csrsrc[pos] = src[i];
    }
}

// ---------------- K3: fused GAT softmax + aggregation + pool --------------
// warp per destination node (8 nodes/block); lane-parallel exp; pad-free
// gather (LDG.64+LDG.32 per edge per lane); block-level smem pooling
// (graph_id sorted -> blocks are ~always single-graph).
__global__ void __launch_bounds__(256) k_gat(
    const int* __restrict__ graph_id, const float* __restrict__ bias, int N)
{
    __shared__ float s_pool[64];
    __shared__ int s_gid;
    const int tid = threadIdx.x;
    const int lane = tid & 31;
    const int node = (blockIdx.x << 3) + (tid >> 5);

    if (tid < 64) s_pool[tid] = 0.f;
    if (tid == 0) {
        int n0 = blockIdx.x << 3;
        s_gid = graph_id[n0 < N ? n0 : (N - 1)];
    }
    __syncthreads();

    const bool vn = node < N;
    const int begin = vn ? g_rowoff[node] : 0;
    const int end   = vn ? g_rowoff[node + 1] : 0;
    const float4 er = vn ? g_er4[node] : make_float4(0.f, 0.f, 0.f, 0.f);

    float s0 = 0.f, s1 = 0.f, s2 = 0.f;
    float a0 = 0.f, a1 = 0.f, a2 = 0.f, a3 = 0.f, a4 = 0.f, a5 = 0.f;

    for (int b = begin; b < end; b += 32) {
        const int i = b + lane;
        const bool act = i < end;
        int mys = act ? g_csrsrc[i] : 0;
        float4 el = g_el4[mys];
        float ex0 = __expf(leaky(el.x + er.x));
        float ex1 = __expf(leaky(el.y + er.y));
        float ex2 = __expf(leaky(el.z + er.z));
        if (act) { s0 += ex0; s1 += ex1; s2 += ex2; }

        int cnt = end - b; if (cnt > 32) cnt = 32;
        #pragma unroll 8
        for (int j = 0; j < cnt; j++) {
            int   s  = __shfl_sync(0xffffffffu, mys, j);
            float e0 = __shfl_sync(0xffffffffu, ex0, j);
            float e1 = __shfl_sync(0xffffffffu, ex1, j);
            float e2 = __shfl_sync(0xffffffffu, ex2, j);
            uint2 u01 = __ldg(&g_featP[(size_t)s * 32 + lane]);
            unsigned int u2 = __ldg(&g_featQ[(size_t)s * 32 + lane]);
            float2 f0 = __bfloat1622float2(*(__nv_bfloat162*)&u01.x);
            float2 f1 = __bfloat1622float2(*(__nv_bfloat162*)&u01.y);
            float2 f2 = __bfloat1622float2(*(__nv_bfloat162*)&u2);
            a0 += e0 * f0.x;  a1 += e0 * f0.y;
            a2 += e1 * f1.x;  a3 += e1 * f1.y;
            a4 += e2 * f2.x;  a5 += e2 * f2.y;
        }
    }

    #pragma unroll
    for (int o = 16; o > 0; o >>= 1) {
        s0 += __shfl_xor_sync(0xffffffffu, s0, o);
        s1 += __shfl_xor_sync(0xffffffffu, s1, o);
        s2 += __shfl_xor_sync(0xffffffffu, s2, o);
    }

    const bool has = end > begin;
    const float i0 = has ? 1.f / s0 : 0.f;
    const float i1 = has ? 1.f / s1 : 0.f;
    const float i2 = has ? 1.f / s2 : 0.f;

    const int d0 = 2 * lane, d1 = 2 * lane + 1;
    const float third = 1.f / 3.f;
    float hd0 = (a0 * i0 + a2 * i1 + a4 * i2
                 + bias[d0] + bias[64 + d0] + bias[128 + d0]) * third;
    float hd1 = (a1 * i0 + a3 * i1 + a5 * i2
                 + bias[d1] + bias[64 + d1] + bias[128 + d1]) * third;

    if (vn) {
        int g = graph_id[node];
        if (g == s_gid) {
            atomicAdd(&s_pool[d0], hd0);
            atomicAdd(&s_pool[d1], hd1);
        } else {
            atomicAdd(&g_pool[g * HID + d0], hd0);
            atomicAdd(&g_pool[g * HID + d1], hd1);
        }
    }
    __syncthreads();
    if (tid < 64) atomicAdd(&g_pool[s_gid * HID + tid], s_pool[tid]);
}

// ---------------- K4: final MLP + sigmoid (+ pool reset) ----------------
// graph counts recovered by binary search over the SORTED graph_id.
__device__ __forceinline__ int lbound(const int* __restrict__ a, int n, int key) {
    int lo = 0, hi = n;
    while (lo < hi) {
        int mid = (lo + hi) >> 1;
        if (a[mid] < key) lo = mid + 1; else hi = mid;
    }
    return lo;
}

__global__ void k_final(
    const float* __restrict__ z, const float* __restrict__ lin1_w,
    const float* __restrict__ lin1_b, const float* __restrict__ lin2_w,
    const float* __restrict__ lin2_b, const int* __restrict__ graph_id,
    float* __restrict__ out, int G, int N)
{
    const int w = threadIdx.x >> 5;
    const int lane = threadIdx.x & 31;
    if (w >= G) return;

    float z1a = lin1_b[lane], z1b = lin1_b[lane + 32];
    const float* zr = &z[w * 128];
    const float* w1a = &lin1_w[lane * 128];
    const float* w1b = &lin1_w[(lane + 32) * 128];
    #pragma unroll 4
    for (int k = 0; k < 128; k++) {
        float zv = zr[k];
        z1a += zv * w1a[k];
        z1b += zv * w1b[k];
    }

    int cnt = 0;
    if (lane == 0)
        cnt = lbound(graph_id, N, w + 1) - lbound(graph_id, N, w);
    cnt = __shfl_sync(0xffffffffu, cnt, 0);

    float invc = 1.f / fmaxf((float)cnt, 1.f);
    float pa = g_pool[w * HID + lane] * invc;
    float pb = g_pool[w * HID + 32 + lane] * invc;

    // self-clean for next run
    g_pool[w * HID + lane] = 0.f;
    g_pool[w * HID + 32 + lane] = 0.f;

    float part = lin2_w[lane] * pa + lin2_w[32 + lane] * pb
               + lin2_w[64 + lane] * z1a + lin2_w[96 + lane] * z1b;
    #pragma unroll
    for (int o = 16; o > 0; o >>= 1)
        part += __shfl_down_sync(0xffffffffu, part, o);

    if (lane == 0) {
        float v = part + lin2_b[0];
        out[w] = 1.f / (1.f + expf(-v));
    }
}

// ---------------- launch ----------------
extern "C" void kernel_launch(void* const* d_in, const int* in_sizes, int n_in,
                              void* d_out, int out_size)
{
    const float* h        = (const float*)d_in[0];
    const float* z        = (const float*)d_in[1];
    const int*   src      = (const int*)  d_in[2];
    const int*   dst      = (const int*)  d_in[3];
    const int*   graph_id = (const int*)  d_in[4];
    const float* fc_w     = (const float*)d_in[5];
    const float* attn_l   = (const float*)d_in[6];
    const float* attn_r   = (const float*)d_in[7];
    const float* bias     = (const float*)d_in[8];
    const float* lin1_w   = (const float*)d_in[9];
    const float* lin1_b   = (const float*)d_in[10];
    const float* lin2_w   = (const float*)d_in[11];
    const float* lin2_b   = (const float*)d_in[12];

    const int N = in_sizes[0] / NODE_DIM;   // 50000
    const int E = in_sizes[2];              // 800000
    const int G = in_sizes[1] / 128;        // 16
    const int NB = (N + SCAN_B - 1) / SCAN_B;  // 49

    // Launch order: slot 4 (the ncu-profiled launch) = k_gat.
    k_gemm<<<(N + GM_BM - 1) / GM_BM, 512>>>(h, fc_w, attn_l, attn_r,  // 1
                                             dst, E, N);
    k_scan_lookback<<<NB, SCAN_B>>>(N);                                // 2
    k_scatter<<<(E + 255) / 256, 256>>>(src, dst, E);                  // 3
    k_gat<<<(N + 7) / 8, 256>>>(graph_id, bias, N);                    // 4
    k_final<<<1, 32 * G>>>(z, lin1_w, lin1_b, lin2_w, lin2_b,          // 5
                           graph_id, (float*)d_out, G, N);
}

// round 14
// speedup vs baseline: 2.4517x; 1.4044x over previous
#include <cuda_runtime.h>
#include <cuda_bf16.h>
#include <math.h>

// Problem constants (shapes fixed by the reference)
#define MAX_N 50000
#define MAX_E 800000
#define MAX_G 16
#define NODE_DIM 128
#define HID 64
#define HEADS 3
#define FDIM 192            // HEADS*HID
#define NEG_SLOPE 0.2f
#define SCAN_B 1024
#define MAX_BLKS 64         // ceil(50000/1024)=49

// ------------- device scratch (static; zero-init from BSS at load) --------
// Self-cleaning invariants (hold at entry of every kernel_launch call):
//   g_deg == 0          (reset by k_scan_lookback after consuming)
//   g_sumflag == 0      (reset by k_scatter)
//   g_pool == 0         (reset by k_final)
// Feat layout (pad-free): per node, lane l owns dims (2l,2l+1) of each head.
//   g_featP[node*32+l] = uint2 {head0 bf16x2, head1 bf16x2}   (12.8 MB)
//   g_featQ[node*32+l] = uint  {head2 bf16x2}                 ( 6.4 MB)
__device__ uint2  g_featP[(size_t)MAX_N * 32];
__device__ unsigned int g_featQ[(size_t)MAX_N * 32];
__device__ __nv_bfloat162 g_wb2[FDIM * 64];              // fc_w in bf16 [192][128]
__device__ float4 g_el4[MAX_N];                          // x,y,z used
__device__ float4 g_er4[MAX_N];
__device__ int    g_deg[MAX_N];
__device__ int    g_sumflag[MAX_BLKS];                   // tile_sum+1, 0=not ready
__device__ int    g_rowoff[MAX_N + 1];
__device__ int    g_cursor[MAX_N];
__device__ int    g_csrsrc[MAX_E];
__device__ float  g_pool[MAX_G * HID];

// ---------------- helpers ----------------
__device__ __forceinline__ float leaky(float x) {
    return x > 0.f ? x : NEG_SLOPE * x;
}
__device__ __forceinline__ void ldsm4(unsigned* r, unsigned addr) {
    asm volatile("ldmatrix.sync.aligned.m8n8.x4.shared.b16 {%0,%1,%2,%3}, [%4];"
                 : "=r"(r[0]), "=r"(r[1]), "=r"(r[2]), "=r"(r[3]) : "r"(addr));
}
__device__ __forceinline__ void mma16816(float* d, const unsigned* a,
                                         const unsigned* b) {
    asm volatile(
        "mma.sync.aligned.m16n8k16.row.col.f32.bf16.bf16.f32 "
        "{%0,%1,%2,%3}, {%4,%5,%6,%7}, {%8,%9}, {%0,%1,%2,%3};"
        : "+f"(d[0]), "+f"(d[1]), "+f"(d[2]), "+f"(d[3])
        : "r"(a[0]), "r"(a[1]), "r"(a[2]), "r"(a[3]), "r"(b[0]), "r"(b[1]));
}

// ---------------- K0: fc_w fp32 -> bf16 (once per run; W stays L2-hot) ----
__global__ void k_wcvt(const float* __restrict__ fc_w) {
    int i = blockIdx.x * blockDim.x + threadIdx.x;
    if (i < FDIM * 64) {
        float2 f = ((const float2*)fc_w)[i];
        g_wb2[i] = __floats2bfloat162_rn(f.x, f.y);
    }
}

// ---- K1: bf16 HMMA GEMM (mma.sync m16n8k16), fused el/er + feat stores,
//      PLUS embedded degree histogram. 512 thr, 64 nodes x 192 cols. ----
// smem: a_s [64][136] bf16 (17408B), b_s [192][136] bf16 (52224B),
//       s_e/s_r [4 nw][64][3] floats (6144B). Stride 136 bf16 = 272B:
//       ldmatrix 8-row phases hit banks {0,4,...,28} — conflict-free.
#define GM_BM 64
#define A_BYTES (64 * 136 * 2)
#define B_BYTES (192 * 136 * 2)
#define SE_OFF  (A_BYTES + B_BYTES)
#define GM_SMEM (SE_OFF + 4 * 64 * 3 * 4 * 2)

__global__ void __launch_bounds__(512) k_gemm(
    const float* __restrict__ h, const float* __restrict__ attn_l,
    const float* __restrict__ attn_r, const int* __restrict__ dst,
    int E, int N)
{
    extern __shared__ char dsm[];
    __nv_bfloat16* a_s = (__nv_bfloat16*)dsm;
    float* s_e = (float*)(dsm + SE_OFF);          // [4][64][3]
    float* s_r = s_e + 4 * 64 * 3;

    const int tid = threadIdx.x;
    const int lane = tid & 31;
    const int warp = tid >> 5;
    const int mw = warp & 3;           // rows 16*mw .. +15
    const int nw = warp >> 2;          // cols 48*nw .. +47
    const int g   = lane >> 2;
    const int tig = lane & 3;
    const int base = blockIdx.x * GM_BM;

    const unsigned sa = (unsigned)__cvta_generic_to_shared(dsm);
    const unsigned sb = sa + A_BYTES;

    // ---- stage A: h fp32 -> bf16 smem [64][136] ----
    const float4* h4 = (const float4*)h;          // [N][32]
    #pragma unroll
    for (int i = 0; i < 4; i++) {
        int F = i * 512 + tid;
        int nd = F >> 5, kq = F & 31;             // node 0..63, float4 idx
        int gn = base + nd;
        float4 v = (gn < N) ? h4[(size_t)gn * 32 + kq]
                            : make_float4(0.f, 0.f, 0.f, 0.f);
        __nv_bfloat162 b0 = __floats2bfloat162_rn(v.x, v.y);
        __nv_bfloat162 b1 = __floats2bfloat162_rn(v.z, v.w);
        *(__nv_bfloat162*)((char*)a_s + nd * 272 + kq * 8)     = b0;
        *(__nv_bfloat162*)((char*)a_s + nd * 272 + kq * 8 + 4) = b1;
    }
    // ---- stage B: g_wb2 (packed bf16) -> smem [192][136] ----
    // Each W row = 128 bf16 = 256 B = 16 uint4. 192 rows * 16 = 3072 = 6*512.
    const uint4* wb4 = (const uint4*)g_wb2;       // [192][16 uint4]
    #pragma unroll
    for (int i = 0; i < 6; i++) {
        int F = i * 512 + tid;
        int c = F >> 4, q = F & 15;               // row, uint4-in-row
        uint4 u = wb4[c * 16 + q];
        *(uint4*)(dsm + A_BYTES + c * 272 + q * 16) = u;
    }
    __syncthreads();

    // ---- ldmatrix source addresses ----
    const int row_a = 16 * mw + (lane & 7) + ((lane >> 3) & 1) * 8;
    const unsigned a_addr0 = sa + row_a * 272 + (lane >> 4) * 16;
    unsigned b_addr0[3];
    #pragma unroll
    for (int j = 0; j < 3; j++) {
        int row_b = 48 * nw + 16 * j + (lane & 7) + ((lane >> 4) & 1) * 8;
        b_addr0[j] = sb + row_b * 272 + ((lane >> 3) & 1) * 16;
    }

    float acc[6][4];
    #pragma unroll
    for (int j = 0; j < 6; j++)
        #pragma unroll
        for (int q = 0; q < 4; q++) acc[j][q] = 0.f;

    #pragma unroll
    for (int ks = 0; ks < 8; ks++) {
        unsigned a[4];
        ldsm4(a, a_addr0 + ks * 32);
        unsigned b[3][4];
        #pragma unroll
        for (int j = 0; j < 3; j++) ldsm4(b[j], b_addr0[j] + ks * 32);
        #pragma unroll
        for (int j = 0; j < 3; j++) {
            mma16816(acc[2 * j],     a, &b[j][0]);
            mma16816(acc[2 * j + 1], a, &b[j][2]);
        }
    }

    // ---- epilogue: feat bf16 stores + el/er ----
    const int node0 = base + 16 * mw + g;     // rows: node0, node0+8
    const int node1 = node0 + 8;
    float e0a[3] = {0.f, 0.f, 0.f}, r0a[3] = {0.f, 0.f, 0.f};
    float e1a[3] = {0.f, 0.f, 0.f}, r1a[3] = {0.f, 0.f, 0.f};

    char* pp0 = (char*)g_featP + (size_t)node0 * 256;
    char* qq0 = (char*)g_featQ + (size_t)node0 * 128;
    char* pp1 = (char*)g_featP + (size_t)node1 * 256;
    char* qq1 = (char*)g_featQ + (size_t)node1 * 128;

    #pragma unroll
    for (int j = 0; j < 6; j++) {
        const int c = 48 * nw + 8 * j + 2 * tig;   // even; c,c+1 same head
        const int hd = c >> 6;
        const int p = (c & 63) >> 1;
        float al0 = __ldg(&attn_l[c]), al1 = __ldg(&attn_l[c + 1]);
        float ar0 = __ldg(&attn_r[c]), ar1 = __ldg(&attn_r[c + 1]);
        e0a[hd] += acc[j][0] * al0 + acc[j][1] * al1;
        r0a[hd] += acc[j][0] * ar0 + acc[j][1] * ar1;
        e1a[hd] += acc[j][2] * al0 + acc[j][3] * al1;
        r1a[hd] += acc[j][2] * ar0 + acc[j][3] * ar1;
        __nv_bfloat162 u0 = __floats2bfloat162_rn(acc[j][0], acc[j][1]);
        __nv_bfloat162 u1 = __floats2bfloat162_rn(acc[j][2], acc[j][3]);
        if (node0 < N) {
            if (hd < 2) *(__nv_bfloat162*)(pp0 + p * 8 + hd * 4) = u0;
            else        *(__nv_bfloat162*)(qq0 + p * 4) = u0;
        }
        if (node1 < N) {
            if (hd < 2) *(__nv_bfloat162*)(pp1 + p * 8 + hd * 4) = u1;
            else        *(__nv_bfloat162*)(qq1 + p * 4) = u1;
        }
    }

    // quad-reduce (lanes 4g..4g+3 share a row)
    #pragma unroll
    for (int o = 1; o <= 2; o <<= 1) {
        #pragma unroll
        for (int hd = 0; hd < 3; hd++) {
            e0a[hd] += __shfl_xor_sync(0xffffffffu, e0a[hd], o);
            r0a[hd] += __shfl_xor_sync(0xffffffffu, r0a[hd], o);
            e1a[hd] += __shfl_xor_sync(0xffffffffu, e1a[hd], o);
            r1a[hd] += __shfl_xor_sync(0xffffffffu, r1a[hd], o);
        }
    }
    if (tig == 0) {
        int nl0 = 16 * mw + g, nl1 = nl0 + 8;
        #pragma unroll
        for (int hd = 0; hd < 3; hd++) {
            s_e[(nw * 64 + nl0) * 3 + hd] = e0a[hd];
            s_r[(nw * 64 + nl0) * 3 + hd] = r0a[hd];
            s_e[(nw * 64 + nl1) * 3 + hd] = e1a[hd];
            s_r[(nw * 64 + nl1) * 3 + hd] = r1a[hd];
        }
    }
    __syncthreads();
    if (tid < GM_BM) {
        int node = base + tid;
        if (node < N) {
            float el[3], er[3];
            #pragma unroll
            for (int hd = 0; hd < 3; hd++) {
                el[hd] = s_e[(0 * 64 + tid) * 3 + hd] + s_e[(1 * 64 + tid) * 3 + hd]
                       + s_e[(2 * 64 + tid) * 3 + hd] + s_e[(3 * 64 + tid) * 3 + hd];
                er[hd] = s_r[(0 * 64 + tid) * 3 + hd] + s_r[(1 * 64 + tid) * 3 + hd]
                       + s_r[(2 * 64 + tid) * 3 + hd] + s_r[(3 * 64 + tid) * 3 + hd];
            }
            g_el4[node] = make_float4(el[0], el[1], el[2], 0.f);
            g_er4[node] = make_float4(er[0], er[1], er[2], 0.f);
        }
    }

    // ---- embedded degree histogram: this block's slice of edges ----
    {
        int eb = (E + gridDim.x - 1) / gridDim.x;
        int e0 = blockIdx.x * eb;
        int e1 = e0 + eb; if (e1 > E) e1 = E;
        for (int i = e0 + tid; i < e1; i += 512)
            atomicAdd(&g_deg[dst[i]], 1);
    }
}

// ------- CSR scan: single kernel, decoupled lookback (49 blocks, all
//         resident -> spin-safe). Also resets g_deg. --------------------
__global__ void __launch_bounds__(SCAN_B) k_scan_lookback(int N) {
    __shared__ int wsum[32];
    __shared__ int s_total;
    __shared__ int s_off;
    const int t = threadIdx.x, lane = t & 31, w = t >> 5;
    if (t == 0) s_off = 0;

    int idx = blockIdx.x * SCAN_B + t;
    int v = (idx < N) ? g_deg[idx] : 0;
    int x = v;
    #pragma unroll
    for (int o = 1; o < 32; o <<= 1) {
        int y = __shfl_up_sync(0xffffffffu, x, o);
        if (lane >= o) x += y;
    }
    if (lane == 31) wsum[w] = x;
    __syncthreads();
    if (w == 0) {
        int s = wsum[lane], sc = s;
        #pragma unroll
        for (int o = 1; o < 32; o <<= 1) {
            int y = __shfl_up_sync(0xffffffffu, sc, o);
            if (lane >= o) sc += y;
        }
        if (lane == 31) s_total = sc;
        wsum[lane] = sc - s;
    }
    __syncthreads();
    const int excl = (x - v) + wsum[w];

    if (t == 0) {
        int S = s_total;
        __threadfence();
        *(volatile int*)&g_sumflag[blockIdx.x] = S + 1;
    }
    if (t < blockIdx.x) {
        volatile int* sf = g_sumflag;
        int tv;
        do { tv = sf[t]; } while (tv == 0);
        atomicAdd(&s_off, tv - 1);
    }
    __syncthreads();
    const int off = s_off;

    if (idx < N) {
        int ro = excl + off;
        g_rowoff[idx] = ro;
        g_cursor[idx] = ro;
        g_deg[idx] = 0;                      // self-clean
        if (idx == N - 1) g_rowoff[N] = ro + v;
    }
}

// ---------------- CSR scatter (+ sumflag reset) ----------------
__global__ void k_scatter(const int* __restrict__ src, const int* __restrict__ dst, int E) {
    if (blockIdx.x == 0 && threadIdx.x < MAX_BLKS)
        g_sumflag[threadIdx.x] = 0;          // self-clean for next run
    int i = blockIdx.x * blockDim.x + threadIdx.x;
    if (i < E) {
        int d = dst[i];
        int pos = atomicAdd(&g_cursor[d], 1);
        g_csrsrc[pos] = src[i];
    }
}

// ---------------- K3: fused GAT softmax + aggregation + pool --------------
__global__ void __launch_bounds__(256) k_gat(
    const int* __restrict__ graph_id, const float* __restrict__ bias, int N)
{
    __shared__ float s_pool[64];
    __shared__ int s_gid;
    const int tid = threadIdx.x;
    const int lane = tid & 31;
    const int node = (blockIdx.x << 3) + (tid >> 5);

    if (tid < 64) s_pool[tid] = 0.f;
    if (tid == 0) {
        int n0 = blockIdx.x << 3;
        s_gid = graph_id[n0 < N ? n0 : (N - 1)];
    }
    __syncthreads();

    const bool vn = node < N;
    const int begin = vn ? g_rowoff[node] : 0;
    const int end   = vn ? g_rowoff[node + 1] : 0;
    const float4 er = vn ? g_er4[node] : make_float4(0.f, 0.f, 0.f, 0.f);

    float s0 = 0.f, s1 = 0.f, s2 = 0.f;
    float a0 = 0.f, a1 = 0.f, a2 = 0.f, a3 = 0.f, a4 = 0.f, a5 = 0.f;

    for (int b = begin; b < end; b += 32) {
        const int i = b + lane;
        const bool act = i < end;
        int mys = act ? g_csrsrc[i] : 0;
        float4 el = g_el4[mys];
        float ex0 = __expf(leaky(el.x + er.x));
        float ex1 = __expf(leaky(el.y + er.y));
        float ex2 = __expf(leaky(el.z + er.z));
        if (act) { s0 += ex0; s1 += ex1; s2 += ex2; }

        int cnt = end - b; if (cnt > 32) cnt = 32;
        #pragma unroll 8
        for (int j = 0; j < cnt; j++) {
            int   s  = __shfl_sync(0xffffffffu, mys, j);
            float e0 = __shfl_sync(0xffffffffu, ex0, j);
            float e1 = __shfl_sync(0xffffffffu, ex1, j);
            float e2 = __shfl_sync(0xffffffffu, ex2, j);
            uint2 u01 = __ldg(&g_featP[(size_t)s * 32 + lane]);
            unsigned int u2 = __ldg(&g_featQ[(size_t)s * 32 + lane]);
            float2 f0 = __bfloat1622float2(*(__nv_bfloat162*)&u01.x);
            float2 f1 = __bfloat1622float2(*(__nv_bfloat162*)&u01.y);
            float2 f2 = __bfloat1622float2(*(__nv_bfloat162*)&u2);
            a0 += e0 * f0.x;  a1 += e0 * f0.y;
            a2 += e1 * f1.x;  a3 += e1 * f1.y;
            a4 += e2 * f2.x;  a5 += e2 * f2.y;
        }
    }

    #pragma unroll
    for (int o = 16; o > 0; o >>= 1) {
        s0 += __shfl_xor_sync(0xffffffffu, s0, o);
        s1 += __shfl_xor_sync(0xffffffffu, s1, o);
        s2 += __shfl_xor_sync(0xffffffffu, s2, o);
    }

    const bool has = end > begin;
    const float i0 = has ? 1.f / s0 : 0.f;
    const float i1 = has ? 1.f / s1 : 0.f;
    const float i2 = has ? 1.f / s2 : 0.f;

    const int d0 = 2 * lane, d1 = 2 * lane + 1;
    const float third = 1.f / 3.f;
    float hd0 = (a0 * i0 + a2 * i1 + a4 * i2
                 + bias[d0] + bias[64 + d0] + bias[128 + d0]) * third;
    float hd1 = (a1 * i0 + a3 * i1 + a5 * i2
                 + bias[d1] + bias[64 + d1] + bias[128 + d1]) * third;

    if (vn) {
        int g = graph_id[node];
        if (g == s_gid) {
            atomicAdd(&s_pool[d0], hd0);
            atomicAdd(&s_pool[d1], hd1);
        } else {
            atomicAdd(&g_pool[g * HID + d0], hd0);
            atomicAdd(&g_pool[g * HID + d1], hd1);
        }
    }
    __syncthreads();
    if (tid < 64) atomicAdd(&g_pool[s_gid * HID + tid], s_pool[tid]);
}

// ---------------- K4: final MLP + sigmoid (+ pool reset) ----------------
__device__ __forceinline__ int lbound(const int* __restrict__ a, int n, int key) {
    int lo = 0, hi = n;
    while (lo < hi) {
        int mid = (lo + hi) >> 1;
        if (a[mid] < key) lo = mid + 1; else hi = mid;
    }
    return lo;
}

__global__ void k_final(
    const float* __restrict__ z, const float* __restrict__ lin1_w,
    const float* __restrict__ lin1_b, const float* __restrict__ lin2_w,
    const float* __restrict__ lin2_b, const int* __restrict__ graph_id,
    float* __restrict__ out, int G, int N)
{
    const int w = threadIdx.x >> 5;
    const int lane = threadIdx.x & 31;
    if (w >= G) return;

    float z1a = lin1_b[lane], z1b = lin1_b[lane + 32];
    const float* zr = &z[w * 128];
    const float* w1a = &lin1_w[lane * 128];
    const float* w1b = &lin1_w[(lane + 32) * 128];
    #pragma unroll 4
    for (int k = 0; k < 128; k++) {
        float zv = zr[k];
        z1a += zv * w1a[k];
        z1b += zv * w1b[k];
    }

    int cnt = 0;
    if (lane == 0)
        cnt = lbound(graph_id, N, w + 1) - lbound(graph_id, N, w);
    cnt = __shfl_sync(0xffffffffu, cnt, 0);

    float invc = 1.f / fmaxf((float)cnt, 1.f);
    float pa = g_pool[w * HID + lane] * invc;
    float pb = g_pool[w * HID + 32 + lane] * invc;

    g_pool[w * HID + lane] = 0.f;
    g_pool[w * HID + 32 + lane] = 0.f;

    float part = lin2_w[lane] * pa + lin2_w[32 + lane] * pb
               + lin2_w[64 + lane] * z1a + lin2_w[96 + lane] * z1b;
    #pragma unroll
    for (int o = 16; o > 0; o >>= 1)
        part += __shfl_down_sync(0xffffffffu, part, o);

    if (lane == 0) {
        float v = part + lin2_b[0];
        out[w] = 1.f / (1.f + expf(-v));
    }
}

// ---------------- launch ----------------
extern "C" void kernel_launch(void* const* d_in, const int* in_sizes, int n_in,
                              void* d_out, int out_size)
{
    const float* h        = (const float*)d_in[0];
    const float* z        = (const float*)d_in[1];
    const int*   src      = (const int*)  d_in[2];
    const int*   dst      = (const int*)  d_in[3];
    const int*   graph_id = (const int*)  d_in[4];
    const float* fc_w     = (const float*)d_in[5];
    const float* attn_l   = (const float*)d_in[6];
    const float* attn_r   = (const float*)d_in[7];
    const float* bias     = (const float*)d_in[8];
    const float* lin1_w   = (const float*)d_in[9];
    const float* lin1_b   = (const float*)d_in[10];
    const float* lin2_w   = (const float*)d_in[11];
    const float* lin2_b   = (const float*)d_in[12];

    const int N = in_sizes[0] / NODE_DIM;   // 50000
    const int E = in_sizes[2];              // 800000
    const int G = in_sizes[1] / 128;        // 16
    const int NB = (N + SCAN_B - 1) / SCAN_B;  // 49

    cudaFuncSetAttribute(k_gemm, cudaFuncAttributeMaxDynamicSharedMemorySize,
                         GM_SMEM);

    k_wcvt<<<(FDIM * 64 + 255) / 256, 256>>>(fc_w);                    // 1
    k_gemm<<<(N + GM_BM - 1) / GM_BM, 512, GM_SMEM>>>(h, attn_l,       // 2
                                                      attn_r, dst, E, N);
    k_scan_lookback<<<NB, SCAN_B>>>(N);                                // 3
    k_scatter<<<(E + 255) / 256, 256>>>(src, dst, E);                  // 4
    k_gat<<<(N + 7) / 8, 256>>>(graph_id, bias, N);                    // 5
    k_final<<<1, 32 * G>>>(z, lin1_w, lin1_b, lin2_w, lin2_b,          // 6
                           graph_id, (float*)d_out, G, N);
}

// round 15
// speedup vs baseline: 2.4585x; 1.0028x over previous
#include <cuda_runtime.h>
#include <cuda_bf16.h>
#include <math.h>

// Problem constants (shapes fixed by the reference)
#define MAX_N 50000
#define MAX_E 800000
#define MAX_G 16
#define NODE_DIM 128
#define HID 64
#define HEADS 3
#define FDIM 192            // HEADS*HID
#define NEG_SLOPE 0.2f
#define SCAN_B 1024
#define MAX_BLKS 64         // ceil(50000/1024)=49

// ------------- device scratch (static; zero-init from BSS at load) --------
// Self-cleaning invariants (hold at entry of every kernel_launch call):
//   g_deg == 0          (reset by k_scan_lookback after consuming)
//   g_sumflag == 0      (reset by k_scatter)
//   g_pool == 0         (reset by k_final)
// Feat layout (pad-free): per node, lane l owns dims (2l,2l+1) of each head.
//   g_featP[node*32+l] = uint2 {head0 bf16x2, head1 bf16x2}   (12.8 MB)
//   g_featQ[node*32+l] = uint  {head2 bf16x2}                 ( 6.4 MB)
__device__ uint2  g_featP[(size_t)MAX_N * 32];
__device__ unsigned int g_featQ[(size_t)MAX_N * 32];
__device__ __nv_bfloat162 g_wb2[FDIM * 64];              // fc_w in bf16 [192][128]
__device__ float4 g_el4[MAX_N];                          // x,y,z used
__device__ float4 g_er4[MAX_N];
__device__ int    g_deg[MAX_N];
__device__ int    g_sumflag[MAX_BLKS];                   // tile_sum+1, 0=not ready
__device__ int    g_rowoff[MAX_N + 1];
__device__ int    g_cursor[MAX_N];
__device__ int    g_csrsrc[MAX_E];
__device__ float  g_pool[MAX_G * HID];

// ---------------- helpers ----------------
__device__ __forceinline__ float leaky(float x) {
    return x > 0.f ? x : NEG_SLOPE * x;
}
__device__ __forceinline__ void ldsm4(unsigned* r, unsigned addr) {
    asm volatile("ldmatrix.sync.aligned.m8n8.x4.shared.b16 {%0,%1,%2,%3}, [%4];"
                 : "=r"(r[0]), "=r"(r[1]), "=r"(r[2]), "=r"(r[3]) : "r"(addr));
}
__device__ __forceinline__ void mma16816(float* d, const unsigned* a,
                                         const unsigned* b) {
    asm volatile(
        "mma.sync.aligned.m16n8k16.row.col.f32.bf16.bf16.f32 "
        "{%0,%1,%2,%3}, {%4,%5,%6,%7}, {%8,%9}, {%0,%1,%2,%3};"
        : "+f"(d[0]), "+f"(d[1]), "+f"(d[2]), "+f"(d[3])
        : "r"(a[0]), "r"(a[1]), "r"(a[2]), "r"(a[3]), "r"(b[0]), "r"(b[1]));
}

// ---------------- K0: fc_w fp32 -> bf16 (once per run; W stays L2-hot) ----
__global__ void k_wcvt(const float* __restrict__ fc_w) {
    int i = blockIdx.x * blockDim.x + threadIdx.x;
    if (i < FDIM * 64) {
        float2 f = ((const float2*)fc_w)[i];
        g_wb2[i] = __floats2bfloat162_rn(f.x, f.y);
    }
}

// ---- K1: bf16 HMMA GEMM (mma.sync m16n8k16), fused el/er + feat stores,
//      PLUS embedded degree histogram. 512 thr, 64 nodes x 192 cols. ----
// smem: a_s [64][136] bf16 (17408B), b_s [192][136] bf16 (52224B),
//       s_e/s_r [4 nw][64][3] floats (6144B). Stride 136 bf16 = 272B:
//       ldmatrix 8-row phases hit banks {0,4,...,28} — conflict-free.
#define GM_BM 64
#define A_BYTES (64 * 136 * 2)
#define B_BYTES (192 * 136 * 2)
#define SE_OFF  (A_BYTES + B_BYTES)
#define GM_SMEM (SE_OFF + 4 * 64 * 3 * 4 * 2)

__global__ void __launch_bounds__(512) k_gemm(
    const float* __restrict__ h, const float* __restrict__ attn_l,
    const float* __restrict__ attn_r, const int* __restrict__ dst,
    int E, int N)
{
    extern __shared__ char dsm[];
    __nv_bfloat16* a_s = (__nv_bfloat16*)dsm;
    float* s_e = (float*)(dsm + SE_OFF);          // [4][64][3]
    float* s_r = s_e + 4 * 64 * 3;

    const int tid = threadIdx.x;
    const int lane = tid & 31;
    const int warp = tid >> 5;
    const int mw = warp & 3;           // rows 16*mw .. +15
    const int nw = warp >> 2;          // cols 48*nw .. +47
    const int g   = lane >> 2;
    const int tig = lane & 3;
    const int base = blockIdx.x * GM_BM;

    const unsigned sa = (unsigned)__cvta_generic_to_shared(dsm);
    const unsigned sb = sa + A_BYTES;

    // ---- stage A: h fp32 -> bf16 smem [64][136] ----
    const float4* h4 = (const float4*)h;          // [N][32]
    #pragma unroll
    for (int i = 0; i < 4; i++) {
        int F = i * 512 + tid;
        int nd = F >> 5, kq = F & 31;             // node 0..63, float4 idx
        int gn = base + nd;
        float4 v = (gn < N) ? h4[(size_t)gn * 32 + kq]
                            : make_float4(0.f, 0.f, 0.f, 0.f);
        __nv_bfloat162 b0 = __floats2bfloat162_rn(v.x, v.y);
        __nv_bfloat162 b1 = __floats2bfloat162_rn(v.z, v.w);
        *(__nv_bfloat162*)((char*)a_s + nd * 272 + kq * 8)     = b0;
        *(__nv_bfloat162*)((char*)a_s + nd * 272 + kq * 8 + 4) = b1;
    }
    // ---- stage B: g_wb2 (packed bf16) -> smem [192][136] ----
    // Each W row = 128 bf16 = 256 B = 16 uint4. 192 rows * 16 = 3072 = 6*512.
    const uint4* wb4 = (const uint4*)g_wb2;       // [192][16 uint4]
    #pragma unroll
    for (int i = 0; i < 6; i++) {
        int F = i * 512 + tid;
        int c = F >> 4, q = F & 15;               // row, uint4-in-row
        uint4 u = wb4[c * 16 + q];
        *(uint4*)(dsm + A_BYTES + c * 272 + q * 16) = u;
    }
    __syncthreads();

    // ---- ldmatrix source addresses ----
    const int row_a = 16 * mw + (lane & 7) + ((lane >> 3) & 1) * 8;
    const unsigned a_addr0 = sa + row_a * 272 + (lane >> 4) * 16;
    unsigned b_addr0[3];
    #pragma unroll
    for (int j = 0; j < 3; j++) {
        int row_b = 48 * nw + 16 * j + (lane & 7) + ((lane >> 4) & 1) * 8;
        b_addr0[j] = sb + row_b * 272 + ((lane >> 3) & 1) * 16;
    }

    float acc[6][4];
    #pragma unroll
    for (int j = 0; j < 6; j++)
        #pragma unroll
        for (int q = 0; q < 4; q++) acc[j][q] = 0.f;

    #pragma unroll
    for (int ks = 0; ks < 8; ks++) {
        unsigned a[4];
        ldsm4(a, a_addr0 + ks * 32);
        unsigned b[3][4];
        #pragma unroll
        for (int j = 0; j < 3; j++) ldsm4(b[j], b_addr0[j] + ks * 32);
        #pragma unroll
        for (int j = 0; j < 3; j++) {
            mma16816(acc[2 * j],     a, &b[j][0]);
            mma16816(acc[2 * j + 1], a, &b[j][2]);
        }
    }

    // ---- epilogue: feat bf16 stores + el/er ----
    const int node0 = base + 16 * mw + g;     // rows: node0, node0+8
    const int node1 = node0 + 8;
    float e0a[3] = {0.f, 0.f, 0.f}, r0a[3] = {0.f, 0.f, 0.f};
    float e1a[3] = {0.f, 0.f, 0.f}, r1a[3] = {0.f, 0.f, 0.f};

    char* pp0 = (char*)g_featP + (size_t)node0 * 256;
    char* qq0 = (char*)g_featQ + (size_t)node0 * 128;
    char* pp1 = (char*)g_featP + (size_t)node1 * 256;
    char* qq1 = (char*)g_featQ + (size_t)node1 * 128;

    #pragma unroll
    for (int j = 0; j < 6; j++) {
        const int c = 48 * nw + 8 * j + 2 * tig;   // even; c,c+1 same head
        const int hd = c >> 6;
        const int p = (c & 63) >> 1;
        float al0 = __ldg(&attn_l[c]), al1 = __ldg(&attn_l[c + 1]);
        float ar0 = __ldg(&attn_r[c]), ar1 = __ldg(&attn_r[c + 1]);
        e0a[hd] += acc[j][0] * al0 + acc[j][1] * al1;
        r0a[hd] += acc[j][0] * ar0 + acc[j][1] * ar1;
        e1a[hd] += acc[j][2] * al0 + acc[j][3] * al1;
        r1a[hd] += acc[j][2] * ar0 + acc[j][3] * ar1;
        __nv_bfloat162 u0 = __floats2bfloat162_rn(acc[j][0], acc[j][1]);
        __nv_bfloat162 u1 = __floats2bfloat162_rn(acc[j][2], acc[j][3]);
        if (node0 < N) {
            if (hd < 2) *(__nv_bfloat162*)(pp0 + p * 8 + hd * 4) = u0;
            else        *(__nv_bfloat162*)(qq0 + p * 4) = u0;
        }
        if (node1 < N) {
            if (hd < 2) *(__nv_bfloat162*)(pp1 + p * 8 + hd * 4) = u1;
            else        *(__nv_bfloat162*)(qq1 + p * 4) = u1;
        }
    }

    // quad-reduce (lanes 4g..4g+3 share a row)
    #pragma unroll
    for (int o = 1; o <= 2; o <<= 1) {
        #pragma unroll
        for (int hd = 0; hd < 3; hd++) {
            e0a[hd] += __shfl_xor_sync(0xffffffffu, e0a[hd], o);
            r0a[hd] += __shfl_xor_sync(0xffffffffu, r0a[hd], o);
            e1a[hd] += __shfl_xor_sync(0xffffffffu, e1a[hd], o);
            r1a[hd] += __shfl_xor_sync(0xffffffffu, r1a[hd], o);
        }
    }
    if (tig == 0) {
        int nl0 = 16 * mw + g, nl1 = nl0 + 8;
        #pragma unroll
        for (int hd = 0; hd < 3; hd++) {
            s_e[(nw * 64 + nl0) * 3 + hd] = e0a[hd];
            s_r[(nw * 64 + nl0) * 3 + hd] = r0a[hd];
            s_e[(nw * 64 + nl1) * 3 + hd] = e1a[hd];
            s_r[(nw * 64 + nl1) * 3 + hd] = r1a[hd];
        }
    }
    __syncthreads();
    if (tid < GM_BM) {
        int node = base + tid;
        if (node < N) {
            float el[3], er[3];
            #pragma unroll
            for (int hd = 0; hd < 3; hd++) {
                el[hd] = s_e[(0 * 64 + tid) * 3 + hd] + s_e[(1 * 64 + tid) * 3 + hd]
                       + s_e[(2 * 64 + tid) * 3 + hd] + s_e[(3 * 64 + tid) * 3 + hd];
                er[hd] = s_r[(0 * 64 + tid) * 3 + hd] + s_r[(1 * 64 + tid) * 3 + hd]
                       + s_r[(2 * 64 + tid) * 3 + hd] + s_r[(3 * 64 + tid) * 3 + hd];
            }
            g_el4[node] = make_float4(el[0], el[1], el[2], 0.f);
            g_er4[node] = make_float4(er[0], er[1], er[2], 0.f);
        }
    }

    // ---- embedded degree histogram: this block's slice of edges ----
    {
        int eb = (E + gridDim.x - 1) / gridDim.x;
        int e0 = blockIdx.x * eb;
        int e1 = e0 + eb; if (e1 > E) e1 = E;
        for (int i = e0 + tid; i < e1; i += 512)
            atomicAdd(&g_deg[dst[i]], 1);
    }
}

// ------- CSR scan: single kernel, decoupled lookback (49 blocks, all
//         resident -> spin-safe). Also resets g_deg. --------------------
__global__ void __launch_bounds__(SCAN_B) k_scan_lookback(int N) {
    __shared__ int wsum[32];
    __shared__ int s_total;
    __shared__ int s_off;
    const int t = threadIdx.x, lane = t & 31, w = t >> 5;
    if (t == 0) s_off = 0;

    int idx = blockIdx.x * SCAN_B + t;
    int v = (idx < N) ? g_deg[idx] : 0;
    int x = v;
    #pragma unroll
    for (int o = 1; o < 32; o <<= 1) {
        int y = __shfl_up_sync(0xffffffffu, x, o);
        if (lane >= o) x += y;
    }
    if (lane == 31) wsum[w] = x;
    __syncthreads();
    if (w == 0) {
        int s = wsum[lane], sc = s;
        #pragma unroll
        for (int o = 1; o < 32; o <<= 1) {
            int y = __shfl_up_sync(0xffffffffu, sc, o);
            if (lane >= o) sc += y;
        }
        if (lane == 31) s_total = sc;
        wsum[lane] = sc - s;
    }
    __syncthreads();
    const int excl = (x - v) + wsum[w];

    if (t == 0) {
        int S = s_total;
        __threadfence();
        *(volatile int*)&g_sumflag[blockIdx.x] = S + 1;
    }
    if (t < blockIdx.x) {
        volatile int* sf = g_sumflag;
        int tv;
        do { tv = sf[t]; } while (tv == 0);
        atomicAdd(&s_off, tv - 1);
    }
    __syncthreads();
    const int off = s_off;

    if (idx < N) {
        int ro = excl + off;
        g_rowoff[idx] = ro;
        g_cursor[idx] = ro;
        g_deg[idx] = 0;                      // self-clean
        if (idx == N - 1) g_rowoff[N] = ro + v;
    }
}

// ---------------- CSR scatter (+ sumflag reset) ----------------
__global__ void k_scatter(const int* __restrict__ src, const int* __restrict__ dst, int E) {
    if (blockIdx.x == 0 && threadIdx.x < MAX_BLKS)
        g_sumflag[threadIdx.x] = 0;          // self-clean for next run
    int i = blockIdx.x * blockDim.x + threadIdx.x;
    if (i < E) {
        int d = dst[i];
        int pos = atomicAdd(&g_cursor[d], 1);
        g_csrsrc[pos] = src[i];
    }
}

// ---------------- K3: fused GAT softmax + aggregation + pool --------------
__global__ void __launch_bounds__(256) k_gat(
    const int* __restrict__ graph_id, const float* __restrict__ bias, int N)
{
    __shared__ float s_pool[64];
    __shared__ int s_gid;
    const int tid = threadIdx.x;
    const int lane = tid & 31;
    const int node = (blockIdx.x << 3) + (tid >> 5);

    if (tid < 64) s_pool[tid] = 0.f;
    if (tid == 0) {
        int n0 = blockIdx.x << 3;
        s_gid = graph_id[n0 < N ? n0 : (N - 1)];
    }
    __syncthreads();

    const bool vn = node < N;
    const int begin = vn ? g_rowoff[node] : 0;
    const int end   = vn ? g_rowoff[node + 1] : 0;
    const float4 er = vn ? g_er4[node] : make_float4(0.f, 0.f, 0.f, 0.f);

    float s0 = 0.f, s1 = 0.f, s2 = 0.f;
    float a0 = 0.f, a1 = 0.f, a2 = 0.f, a3 = 0.f, a4 = 0.f, a5 = 0.f;

    for (int b = begin; b < end; b += 32) {
        const int i = b + lane;
        const bool act = i < end;
        int mys = act ? g_csrsrc[i] : 0;
        float4 el = g_el4[mys];
        float ex0 = __expf(leaky(el.x + er.x));
        float ex1 = __expf(leaky(el.y + er.y));
        float ex2 = __expf(leaky(el.z + er.z));
        if (act) { s0 += ex0; s1 += ex1; s2 += ex2; }

        int cnt = end - b; if (cnt > 32) cnt = 32;
        #pragma unroll 8
        for (int j = 0; j < cnt; j++) {
            int   s  = __shfl_sync(0xffffffffu, mys, j);
            float e0 = __shfl_sync(0xffffffffu, ex0, j);
            float e1 = __shfl_sync(0xffffffffu, ex1, j);
            float e2 = __shfl_sync(0xffffffffu, ex2, j);
            uint2 u01 = __ldg(&g_featP[(size_t)s * 32 + lane]);
            unsigned int u2 = __ldg(&g_featQ[(size_t)s * 32 + lane]);
            float2 f0 = __bfloat1622float2(*(__nv_bfloat162*)&u01.x);
            float2 f1 = __bfloat1622float2(*(__nv_bfloat162*)&u01.y);
            float2 f2 = __bfloat1622float2(*(__nv_bfloat162*)&u2);
            a0 += e0 * f0.x;  a1 += e0 * f0.y;
            a2 += e1 * f1.x;  a3 += e1 * f1.y;
            a4 += e2 * f2.x;  a5 += e2 * f2.y;
        }
    }

    #pragma unroll
    for (int o = 16; o > 0; o >>= 1) {
        s0 += __shfl_xor_sync(0xffffffffu, s0, o);
        s1 += __shfl_xor_sync(0xffffffffu, s1, o);
        s2 += __shfl_xor_sync(0xffffffffu, s2, o);
    }

    const bool has = end > begin;
    const float i0 = has ? 1.f / s0 : 0.f;
    const float i1 = has ? 1.f / s1 : 0.f;
    const float i2 = has ? 1.f / s2 : 0.f;

    const int d0 = 2 * lane, d1 = 2 * lane + 1;
    const float third = 1.f / 3.f;
    float hd0 = (a0 * i0 + a2 * i1 + a4 * i2
                 + bias[d0] + bias[64 + d0] + bias[128 + d0]) * third;
    float hd1 = (a1 * i0 + a3 * i1 + a5 * i2
                 + bias[d1] + bias[64 + d1] + bias[128 + d1]) * third;

    if (vn) {
        int g = graph_id[node];
        if (g == s_gid) {
            atomicAdd(&s_pool[d0], hd0);
            atomicAdd(&s_pool[d1], hd1);
        } else {
            atomicAdd(&g_pool[g * HID + d0], hd0);
            atomicAdd(&g_pool[g * HID + d1], hd1);
        }
    }
    __syncthreads();
    if (tid < 64) atomicAdd(&g_pool[s_gid * HID + tid], s_pool[tid]);
}

// ---------------- K4: final MLP + sigmoid (+ pool reset) ----------------
__device__ __forceinline__ int lbound(const int* __restrict__ a, int n, int key) {
    int lo = 0, hi = n;
    while (lo < hi) {
        int mid = (lo + hi) >> 1;
        if (a[mid] < key) lo = mid + 1; else hi = mid;
    }
    return lo;
}

__global__ void k_final(
    const float* __restrict__ z, const float* __restrict__ lin1_w,
    const float* __restrict__ lin1_b, const float* __restrict__ lin2_w,
    const float* __restrict__ lin2_b, const int* __restrict__ graph_id,
    float* __restrict__ out, int G, int N)
{
    const int w = threadIdx.x >> 5;
    const int lane = threadIdx.x & 31;
    if (w >= G) return;

    float z1a = lin1_b[lane], z1b = lin1_b[lane + 32];
    const float* zr = &z[w * 128];
    const float* w1a = &lin1_w[lane * 128];
    const float* w1b = &lin1_w[(lane + 32) * 128];
    #pragma unroll 4
    for (int k = 0; k < 128; k++) {
        float zv = zr[k];
        z1a += zv * w1a[k];
        z1b += zv * w1b[k];
    }

    int cnt = 0;
    if (lane == 0)
        cnt = lbound(graph_id, N, w + 1) - lbound(graph_id, N, w);
    cnt = __shfl_sync(0xffffffffu, cnt, 0);

    float invc = 1.f / fmaxf((float)cnt, 1.f);
    float pa = g_pool[w * HID + lane] * invc;
    float pb = g_pool[w * HID + 32 + lane] * invc;

    g_pool[w * HID + lane] = 0.f;
    g_pool[w * HID + 32 + lane] = 0.f;

    float part = lin2_w[lane] * pa + lin2_w[32 + lane] * pb
               + lin2_w[64 + lane] * z1a + lin2_w[96 + lane] * z1b;
    #pragma unroll
    for (int o = 16; o > 0; o >>= 1)
        part += __shfl_down_sync(0xffffffffu, part, o);

    if (lane == 0) {
        float v = part + lin2_b[0];
        out[w] = 1.f / (1.f + expf(-v));
    }
}

// ---------------- launch ----------------
extern "C" void kernel_launch(void* const* d_in, const int* in_sizes, int n_in,
                              void* d_out, int out_size)
{
    const float* h        = (const float*)d_in[0];
    const float* z        = (const float*)d_in[1];
    const int*   src      = (const int*)  d_in[2];
    const int*   dst      = (const int*)  d_in[3];
    const int*   graph_id = (const int*)  d_in[4];
    const float* fc_w     = (const float*)d_in[5];
    const float* attn_l   = (const float*)d_in[6];
    const float* attn_r   = (const float*)d_in[7];
    const float* bias     = (const float*)d_in[8];
    const float* lin1_w   = (const float*)d_in[9];
    const float* lin1_b   = (const float*)d_in[10];
    const float* lin2_w   = (const float*)d_in[11];
    const float* lin2_b   = (const float*)d_in[12];

    const int N = in_sizes[0] / NODE_DIM;   // 50000
    const int E = in_sizes[2];              // 800000
    const int G = in_sizes[1] / 128;        // 16
    const int NB = (N + SCAN_B - 1) / SCAN_B;  // 49

    cudaFuncSetAttribute(k_gemm, cudaFuncAttributeMaxDynamicSharedMemorySize,
                         GM_SMEM);

    k_wcvt<<<(FDIM * 64 + 255) / 256, 256>>>(fc_w);                    // 1
    k_gemm<<<(N + GM_BM - 1) / GM_BM, 512, GM_SMEM>>>(h, attn_l,       // 2
                                                      attn_r, dst, E, N);
    k_scan_lookback<<<NB, SCAN_B>>>(N);                                // 3
    k_scatter<<<(E + 255) / 256, 256>>>(src, dst, E);                  // 4
    k_gat<<<(N + 7) / 8, 256>>>(graph_id, bias, N);                    // 5
    k_final<<<1, 32 * G>>>(z, lin1_w, lin1_b, lin2_w, lin2_b,          // 6
                           graph_id, (float*)d_out, G, N);
}

// round 16
// speedup vs baseline: 2.4636x; 1.0021x over previous
#include <cuda_runtime.h>
#include <cuda_bf16.h>
#include <math.h>

// Problem constants (shapes fixed by the reference)
#define MAX_N 50000
#define MAX_E 800000
#define MAX_G 16
#define NODE_DIM 128
#define HID 64
#define HEADS 3
#define FDIM 192            // HEADS*HID
#define NEG_SLOPE 0.2f
#define SCAN_B 1024
#define MAX_BLKS 64         // ceil(50000/1024)=49

// ------------- device scratch (static; zero-init from BSS at load) --------
// Self-cleaning invariants (hold at entry of every kernel_launch call):
//   g_deg == 0          (reset by k_scan_lookback after consuming)
//   g_sumflag == 0      (reset by k_scatter)
//   g_pool == 0         (reset by k_final)
// Feat layout (pad-free): per node, lane l owns dims (2l,2l+1) of each head.
//   g_featP[node*32+l] = uint2 {head0 bf16x2, head1 bf16x2}   (12.8 MB)
//   g_featQ[node*32+l] = uint  {head2 bf16x2}                 ( 6.4 MB)
__device__ uint2  g_featP[(size_t)MAX_N * 32];
__device__ unsigned int g_featQ[(size_t)MAX_N * 32];
__device__ __nv_bfloat162 g_wb2[FDIM * 64];              // fc_w in bf16 [192][128]
__device__ float4 g_el4[MAX_N];                          // x,y,z used
__device__ float4 g_er4[MAX_N];
__device__ int    g_deg[MAX_N];
__device__ int    g_sumflag[MAX_BLKS];                   // tile_sum+1, 0=not ready
__device__ int    g_rowoff[MAX_N + 1];
__device__ int    g_cursor[MAX_N];
__device__ int    g_csrsrc[MAX_E];
__device__ float  g_pool[MAX_G * HID];

// ---------------- helpers ----------------
__device__ __forceinline__ float leaky(float x) {
    return x > 0.f ? x : NEG_SLOPE * x;
}
__device__ __forceinline__ void ldsm4(unsigned* r, unsigned addr) {
    asm volatile("ldmatrix.sync.aligned.m8n8.x4.shared.b16 {%0,%1,%2,%3}, [%4];"
                 : "=r"(r[0]), "=r"(r[1]), "=r"(r[2]), "=r"(r[3]) : "r"(addr));
}
__device__ __forceinline__ void mma16816(float* d, const unsigned* a,
                                         const unsigned* b) {
    asm volatile(
        "mma.sync.aligned.m16n8k16.row.col.f32.bf16.bf16.f32 "
        "{%0,%1,%2,%3}, {%4,%5,%6,%7}, {%8,%9}, {%0,%1,%2,%3};"
        : "+f"(d[0]), "+f"(d[1]), "+f"(d[2]), "+f"(d[3])
        : "r"(a[0]), "r"(a[1]), "r"(a[2]), "r"(a[3]), "r"(b[0]), "r"(b[1]));
}

// ---------------- K0: fc_w fp32 -> bf16 (once per run; W stays L2-hot) ----
__global__ void k_wcvt(const float* __restrict__ fc_w) {
    int i = blockIdx.x * blockDim.x + threadIdx.x;
    if (i < FDIM * 64) {
        float2 f = ((const float2*)fc_w)[i];
        g_wb2[i] = __floats2bfloat162_rn(f.x, f.y);
    }
}

// ---- K1: bf16 HMMA GEMM (mma.sync m16n8k16), fused el/er + feat stores,
//      PLUS embedded degree histogram. 512 thr, 64 nodes x 192 cols. ----
// smem: a_s [64][136] bf16 (17408B), b_s [192][136] bf16 (52224B),
//       s_e/s_r [4 nw][64][3] floats (6144B). Stride 136 bf16 = 272B:
//       ldmatrix 8-row phases hit banks {0,4,...,28} — conflict-free.
#define GM_BM 64
#define A_BYTES (64 * 136 * 2)
#define B_BYTES (192 * 136 * 2)
#define SE_OFF  (A_BYTES + B_BYTES)
#define GM_SMEM (SE_OFF + 4 * 64 * 3 * 4 * 2)

__global__ void __launch_bounds__(512) k_gemm(
    const float* __restrict__ h, const float* __restrict__ attn_l,
    const float* __restrict__ attn_r, const int* __restrict__ dst,
    int E, int N)
{
    extern __shared__ char dsm[];
    __nv_bfloat16* a_s = (__nv_bfloat16*)dsm;
    float* s_e = (float*)(dsm + SE_OFF);          // [4][64][3]
    float* s_r = s_e + 4 * 64 * 3;

    const int tid = threadIdx.x;
    const int lane = tid & 31;
    const int warp = tid >> 5;
    const int mw = warp & 3;           // rows 16*mw .. +15
    const int nw = warp >> 2;          // cols 48*nw .. +47
    const int g   = lane >> 2;
    const int tig = lane & 3;
    const int base = blockIdx.x * GM_BM;

    const unsigned sa = (unsigned)__cvta_generic_to_shared(dsm);
    const unsigned sb = sa + A_BYTES;

    // ---- stage A: h fp32 -> bf16 smem [64][136] ----
    const float4* h4 = (const float4*)h;          // [N][32]
    #pragma unroll
    for (int i = 0; i < 4; i++) {
        int F = i * 512 + tid;
        int nd = F >> 5, kq = F & 31;             // node 0..63, float4 idx
        int gn = base + nd;
        float4 v = (gn < N) ? h4[(size_t)gn * 32 + kq]
                            : make_float4(0.f, 0.f, 0.f, 0.f);
        __nv_bfloat162 b0 = __floats2bfloat162_rn(v.x, v.y);
        __nv_bfloat162 b1 = __floats2bfloat162_rn(v.z, v.w);
        *(__nv_bfloat162*)((char*)a_s + nd * 272 + kq * 8)     = b0;
        *(__nv_bfloat162*)((char*)a_s + nd * 272 + kq * 8 + 4) = b1;
    }
    // ---- stage B: g_wb2 (packed bf16) -> smem [192][136] ----
    // Each W row = 128 bf16 = 256 B = 16 uint4. 192 rows * 16 = 3072 = 6*512.
    const uint4* wb4 = (const uint4*)g_wb2;       // [192][16 uint4]
    #pragma unroll
    for (int i = 0; i < 6; i++) {
        int F = i * 512 + tid;
        int c = F >> 4, q = F & 15;               // row, uint4-in-row
        uint4 u = wb4[c * 16 + q];
        *(uint4*)(dsm + A_BYTES + c * 272 + q * 16) = u;
    }
    __syncthreads();

    // ---- ldmatrix source addresses ----
    const int row_a = 16 * mw + (lane & 7) + ((lane >> 3) & 1) * 8;
    const unsigned a_addr0 = sa + row_a * 272 + (lane >> 4) * 16;
    unsigned b_addr0[3];
    #pragma unroll
    for (int j = 0; j < 3; j++) {
        int row_b = 48 * nw + 16 * j + (lane & 7) + ((lane >> 4) & 1) * 8;
        b_addr0[j] = sb + row_b * 272 + ((lane >> 3) & 1) * 16;
    }

    float acc[6][4];
    #pragma unroll
    for (int j = 0; j < 6; j++)
        #pragma unroll
        for (int q = 0; q < 4; q++) acc[j][q] = 0.f;

    #pragma unroll
    for (int ks = 0; ks < 8; ks++) {
        unsigned a[4];
        ldsm4(a, a_addr0 + ks * 32);
        unsigned b[3][4];
        #pragma unroll
        for (int j = 0; j < 3; j++) ldsm4(b[j], b_addr0[j] + ks * 32);
        #pragma unroll
        for (int j = 0; j < 3; j++) {
            mma16816(acc[2 * j],     a, &b[j][0]);
            mma16816(acc[2 * j + 1], a, &b[j][2]);
        }
    }

    // ---- epilogue: feat bf16 stores + el/er ----
    const int node0 = base + 16 * mw + g;     // rows: node0, node0+8
    const int node1 = node0 + 8;
    float e0a[3] = {0.f, 0.f, 0.f}, r0a[3] = {0.f, 0.f, 0.f};
    float e1a[3] = {0.f, 0.f, 0.f}, r1a[3] = {0.f, 0.f, 0.f};

    char* pp0 = (char*)g_featP + (size_t)node0 * 256;
    char* qq0 = (char*)g_featQ + (size_t)node0 * 128;
    char* pp1 = (char*)g_featP + (size_t)node1 * 256;
    char* qq1 = (char*)g_featQ + (size_t)node1 * 128;

    #pragma unroll
    for (int j = 0; j < 6; j++) {
        const int c = 48 * nw + 8 * j + 2 * tig;   // even; c,c+1 same head
        const int hd = c >> 6;
        const int p = (c & 63) >> 1;
        float al0 = __ldg(&attn_l[c]), al1 = __ldg(&attn_l[c + 1]);
        float ar0 = __ldg(&attn_r[c]), ar1 = __ldg(&attn_r[c + 1]);
        e0a[hd] += acc[j][0] * al0 + acc[j][1] * al1;
        r0a[hd] += acc[j][0] * ar0 + acc[j][1] * ar1;
        e1a[hd] += acc[j][2] * al0 + acc[j][3] * al1;
        r1a[hd] += acc[j][2] * ar0 + acc[j][3] * ar1;
        __nv_bfloat162 u0 = __floats2bfloat162_rn(acc[j][0], acc[j][1]);
        __nv_bfloat162 u1 = __floats2bfloat162_rn(acc[j][2], acc[j][3]);
        if (node0 < N) {
            if (hd < 2) *(__nv_bfloat162*)(pp0 + p * 8 + hd * 4) = u0;
            else        *(__nv_bfloat162*)(qq0 + p * 4) = u0;
        }
        if (node1 < N) {
            if (hd < 2) *(__nv_bfloat162*)(pp1 + p * 8 + hd * 4) = u1;
            else        *(__nv_bfloat162*)(qq1 + p * 4) = u1;
        }
    }

    // quad-reduce (lanes 4g..4g+3 share a row)
    #pragma unroll
    for (int o = 1; o <= 2; o <<= 1) {
        #pragma unroll
        for (int hd = 0; hd < 3; hd++) {
            e0a[hd] += __shfl_xor_sync(0xffffffffu, e0a[hd], o);
            r0a[hd] += __shfl_xor_sync(0xffffffffu, r0a[hd], o);
            e1a[hd] += __shfl_xor_sync(0xffffffffu, e1a[hd], o);
            r1a[hd] += __shfl_xor_sync(0xffffffffu, r1a[hd], o);
        }
    }
    if (tig == 0) {
        int nl0 = 16 * mw + g, nl1 = nl0 + 8;
        #pragma unroll
        for (int hd = 0; hd < 3; hd++) {
            s_e[(nw * 64 + nl0) * 3 + hd] = e0a[hd];
            s_r[(nw * 64 + nl0) * 3 + hd] = r0a[hd];
            s_e[(nw * 64 + nl1) * 3 + hd] = e1a[hd];
            s_r[(nw * 64 + nl1) * 3 + hd] = r1a[hd];
        }
    }
    __syncthreads();
    if (tid < GM_BM) {
        int node = base + tid;
        if (node < N) {
            float el[3], er[3];
            #pragma unroll
            for (int hd = 0; hd < 3; hd++) {
                el[hd] = s_e[(0 * 64 + tid) * 3 + hd] + s_e[(1 * 64 + tid) * 3 + hd]
                       + s_e[(2 * 64 + tid) * 3 + hd] + s_e[(3 * 64 + tid) * 3 + hd];
                er[hd] = s_r[(0 * 64 + tid) * 3 + hd] + s_r[(1 * 64 + tid) * 3 + hd]
                       + s_r[(2 * 64 + tid) * 3 + hd] + s_r[(3 * 64 + tid) * 3 + hd];
            }
            g_el4[node] = make_float4(el[0], el[1], el[2], 0.f);
            g_er4[node] = make_float4(er[0], er[1], er[2], 0.f);
        }
    }

    // ---- embedded degree histogram: this block's slice of edges ----
    {
        int eb = (E + gridDim.x - 1) / gridDim.x;
        int e0 = blockIdx.x * eb;
        int e1 = e0 + eb; if (e1 > E) e1 = E;
        for (int i = e0 + tid; i < e1; i += 512)
            atomicAdd(&g_deg[dst[i]], 1);
    }
}

// ------- CSR scan: single kernel, decoupled lookback (49 blocks, all
//         resident -> spin-safe). Also resets g_deg. --------------------
__global__ void __launch_bounds__(SCAN_B) k_scan_lookback(int N) {
    __shared__ int wsum[32];
    __shared__ int s_total;
    __shared__ int s_off;
    const int t = threadIdx.x, lane = t & 31, w = t >> 5;
    if (t == 0) s_off = 0;

    int idx = blockIdx.x * SCAN_B + t;
    int v = (idx < N) ? g_deg[idx] : 0;
    int x = v;
    #pragma unroll
    for (int o = 1; o < 32; o <<= 1) {
        int y = __shfl_up_sync(0xffffffffu, x, o);
        if (lane >= o) x += y;
    }
    if (lane == 31) wsum[w] = x;
    __syncthreads();
    if (w == 0) {
        int s = wsum[lane], sc = s;
        #pragma unroll
        for (int o = 1; o < 32; o <<= 1) {
            int y = __shfl_up_sync(0xffffffffu, sc, o);
            if (lane >= o) sc += y;
        }
        if (lane == 31) s_total = sc;
        wsum[lane] = sc - s;
    }
    __syncthreads();
    const int excl = (x - v) + wsum[w];

    if (t == 0) {
        int S = s_total;
        __threadfence();
        *(volatile int*)&g_sumflag[blockIdx.x] = S + 1;
    }
    if (t < blockIdx.x) {
        volatile int* sf = g_sumflag;
        int tv;
        do { tv = sf[t]; } while (tv == 0);
        atomicAdd(&s_off, tv - 1);
    }
    __syncthreads();
    const int off = s_off;

    if (idx < N) {
        int ro = excl + off;
        g_rowoff[idx] = ro;
        g_cursor[idx] = ro;
        g_deg[idx] = 0;                      // self-clean
        if (idx == N - 1) g_rowoff[N] = ro + v;
    }
}

// ---------------- CSR scatter (+ sumflag reset) ----------------
__global__ void k_scatter(const int* __restrict__ src, const int* __restrict__ dst, int E) {
    if (blockIdx.x == 0 && threadIdx.x < MAX_BLKS)
        g_sumflag[threadIdx.x] = 0;          // self-clean for next run
    int i = blockIdx.x * blockDim.x + threadIdx.x;
    if (i < E) {
        int d = dst[i];
        int pos = atomicAdd(&g_cursor[d], 1);
        g_csrsrc[pos] = src[i];
    }
}

// ---------------- K3: fused GAT softmax + aggregation + pool --------------
__global__ void __launch_bounds__(256) k_gat(
    const int* __restrict__ graph_id, const float* __restrict__ bias, int N)
{
    __shared__ float s_pool[64];
    __shared__ int s_gid;
    const int tid = threadIdx.x;
    const int lane = tid & 31;
    const int node = (blockIdx.x << 3) + (tid >> 5);

    if (tid < 64) s_pool[tid] = 0.f;
    if (tid == 0) {
        int n0 = blockIdx.x << 3;
        s_gid = graph_id[n0 < N ? n0 : (N - 1)];
    }
    __syncthreads();

    const bool vn = node < N;
    const int begin = vn ? g_rowoff[node] : 0;
    const int end   = vn ? g_rowoff[node + 1] : 0;
    const float4 er = vn ? g_er4[node] : make_float4(0.f, 0.f, 0.f, 0.f);

    float s0 = 0.f, s1 = 0.f, s2 = 0.f;
    float a0 = 0.f, a1 = 0.f, a2 = 0.f, a3 = 0.f, a4 = 0.f, a5 = 0.f;

    for (int b = begin; b < end; b += 32) {
        const int i = b + lane;
        const bool act = i < end;
        int mys = act ? g_csrsrc[i] : 0;
        float4 el = g_el4[mys];
        float ex0 = __expf(leaky(el.x + er.x));
        float ex1 = __expf(leaky(el.y + er.y));
        float ex2 = __expf(leaky(el.z + er.z));
        if (act) { s0 += ex0; s1 += ex1; s2 += ex2; }

        int cnt = end - b; if (cnt > 32) cnt = 32;
        #pragma unroll 8
        for (int j = 0; j < cnt; j++) {
            int   s  = __shfl_sync(0xffffffffu, mys, j);
            float e0 = __shfl_sync(0xffffffffu, ex0, j);
            float e1 = __shfl_sync(0xffffffffu, ex1, j);
            float e2 = __shfl_sync(0xffffffffu, ex2, j);
            uint2 u01 = __ldg(&g_featP[(size_t)s * 32 + lane]);
            unsigned int u2 = __ldg(&g_featQ[(size_t)s * 32 + lane]);
            float2 f0 = __bfloat1622float2(*(__nv_bfloat162*)&u01.x);
            float2 f1 = __bfloat1622float2(*(__nv_bfloat162*)&u01.y);
            float2 f2 = __bfloat1622float2(*(__nv_bfloat162*)&u2);
            a0 += e0 * f0.x;  a1 += e0 * f0.y;
            a2 += e1 * f1.x;  a3 += e1 * f1.y;
            a4 += e2 * f2.x;  a5 += e2 * f2.y;
        }
    }

    #pragma unroll
    for (int o = 16; o > 0; o >>= 1) {
        s0 += __shfl_xor_sync(0xffffffffu, s0, o);
        s1 += __shfl_xor_sync(0xffffffffu, s1, o);
        s2 += __shfl_xor_sync(0xffffffffu, s2, o);
    }

    const bool has = end > begin;
    const float i0 = has ? 1.f / s0 : 0.f;
    const float i1 = has ? 1.f / s1 : 0.f;
    const float i2 = has ? 1.f / s2 : 0.f;

    const int d0 = 2 * lane, d1 = 2 * lane + 1;
    const float third = 1.f / 3.f;
    float hd0 = (a0 * i0 + a2 * i1 + a4 * i2
                 + bias[d0] + bias[64 + d0] + bias[128 + d0]) * third;
    float hd1 = (a1 * i0 + a3 * i1 + a5 * i2
                 + bias[d1] + bias[64 + d1] + bias[128 + d1]) * third;

    if (vn) {
        int g = graph_id[node];
        if (g == s_gid) {
            atomicAdd(&s_pool[d0], hd0);
            atomicAdd(&s_pool[d1], hd1);
        } else {
            atomicAdd(&g_pool[g * HID + d0], hd0);
            atomicAdd(&g_pool[g * HID + d1], hd1);
        }
    }
    __syncthreads();
    if (tid < 64) atomicAdd(&g_pool[s_gid * HID + tid], s_pool[tid]);
}

// ---------------- K4: final MLP + sigmoid (+ pool reset) ----------------
__device__ __forceinline__ int lbound(const int* __restrict__ a, int n, int key) {
    int lo = 0, hi = n;
    while (lo < hi) {
        int mid = (lo + hi) >> 1;
        if (a[mid] < key) lo = mid + 1; else hi = mid;
    }
    return lo;
}

__global__ void k_final(
    const float* __restrict__ z, const float* __restrict__ lin1_w,
    const float* __restrict__ lin1_b, const float* __restrict__ lin2_w,
    const float* __restrict__ lin2_b, const int* __restrict__ graph_id,
    float* __restrict__ out, int G, int N)
{
    const int w = threadIdx.x >> 5;
    const int lane = threadIdx.x & 31;
    if (w >= G) return;

    float z1a = lin1_b[lane], z1b = lin1_b[lane + 32];
    const float* zr = &z[w * 128];
    const float* w1a = &lin1_w[lane * 128];
    const float* w1b = &lin1_w[(lane + 32) * 128];
    #pragma unroll 4
    for (int k = 0; k < 128; k++) {
        float zv = zr[k];
        z1a += zv * w1a[k];
        z1b += zv * w1b[k];
    }

    int cnt = 0;
    if (lane == 0)
        cnt = lbound(graph_id, N, w + 1) - lbound(graph_id, N, w);
    cnt = __shfl_sync(0xffffffffu, cnt, 0);

    float invc = 1.f / fmaxf((float)cnt, 1.f);
    float pa = g_pool[w * HID + lane] * invc;
    float pb = g_pool[w * HID + 32 + lane] * invc;

    g_pool[w * HID + lane] = 0.f;
    g_pool[w * HID + 32 + lane] = 0.f;

    float part = lin2_w[lane] * pa + lin2_w[32 + lane] * pb
               + lin2_w[64 + lane] * z1a + lin2_w[96 + lane] * z1b;
    #pragma unroll
    for (int o = 16; o > 0; o >>= 1)
        part += __shfl_down_sync(0xffffffffu, part, o);

    if (lane == 0) {
        float v = part + lin2_b[0];
        out[w] = 1.f / (1.f + expf(-v));
    }
}

// ---------------- launch ----------------
extern "C" void kernel_launch(void* const* d_in, const int* in_sizes, int n_in,
                              void* d_out, int out_size)
{
    const float* h        = (const float*)d_in[0];
    const float* z        = (const float*)d_in[1];
    const int*   src      = (const int*)  d_in[2];
    const int*   dst      = (const int*)  d_in[3];
    const int*   graph_id = (const int*)  d_in[4];
    const float* fc_w     = (const float*)d_in[5];
    const float* attn_l   = (const float*)d_in[6];
    const float* attn_r   = (const float*)d_in[7];
    const float* bias     = (const float*)d_in[8];
    const float* lin1_w   = (const float*)d_in[9];
    const float* lin1_b   = (const float*)d_in[10];
    const float* lin2_w   = (const float*)d_in[11];
    const float* lin2_b   = (const float*)d_in[12];

    const int N = in_sizes[0] / NODE_DIM;   // 50000
    const int E = in_sizes[2];              // 800000
    const int G = in_sizes[1] / 128;        // 16
    const int NB = (N + SCAN_B - 1) / SCAN_B;  // 49

    cudaFuncSetAttribute(k_gemm, cudaFuncAttributeMaxDynamicSharedMemorySize,
                         GM_SMEM);

    k_wcvt<<<(FDIM * 64 + 255) / 256, 256>>>(fc_w);                    // 1
    k_gemm<<<(N + GM_BM - 1) / GM_BM, 512, GM_SMEM>>>(h, attn_l,       // 2
                                                      attn_r, dst, E, N);
    k_scan_lookback<<<NB, SCAN_B>>>(N);                                // 3
    k_scatter<<<(E + 255) / 256, 256>>>(src, dst, E);                  // 4
    k_gat<<<(N + 7) / 8, 256>>>(graph_id, bias, N);                    // 5
    k_final<<<1, 32 * G>>>(z, lin1_w, lin1_b, lin2_w, lin2_b,          // 6
                           graph_id, (float*)d_out, G, N);
}